// round 2
// baseline (speedup 1.0000x reference)
#include <cuda_runtime.h>
#include <cuda_bf16.h>
#include <math.h>

// Problem constants
#define NN    50000
#define EE    800000
#define IN_F  512
#define HID   256
#define OUT_F 64

// ---------------- scratch (static device globals; no allocs) ----------------
__device__ float g_xw1[(size_t)NN * HID];   // X @ W1
__device__ float g_h  [(size_t)NN * HID];   // relu+dropout(SpMM1)
__device__ float g_hw2[(size_t)NN * OUT_F]; // h @ W2
__device__ int   g_rowptr[NN + 1];
__device__ int   g_is64;                    // 1 if indices are int64, 0 if int32

// ---------------- index dtype detection (int64 vs int32) ---------------------
// a_col is random/unsorted. If the buffer is really int32, reading it as int64
// fuses adjacent pairs -> values >= 2^32 w.h.p. Check 32 probes.
__global__ void detect_idx_kernel(const void* __restrict__ a_col_raw, int E) {
    if (threadIdx.x != 0 || blockIdx.x != 0) return;
    const long long* p = (const long long*)a_col_raw;
    int ok = 1;
    for (int i = 0; i < 16; i++) {
        long long v = p[i];
        if (v < 0 || v >= NN) { ok = 0; break; }
    }
    if (ok) {
        // also probe near the end (int64 layout: E entries valid)
        for (int i = 0; i < 16; i++) {
            long long v = p[E / 2 + i];
            if (v < 0 || v >= NN) { ok = 0; break; }
        }
    }
    g_is64 = ok;
}

__device__ __forceinline__ int load_idx(const void* p, int i, int is64) {
    if (is64) return (int)((const long long*)p)[i];
    return ((const int*)p)[i];
}

// ---------------- rowptr: lower_bound per row over sorted a_row -------------
__global__ void build_rowptr_kernel(const void* __restrict__ a_row, int E) {
    int r = blockIdx.x * blockDim.x + threadIdx.x;
    if (r > NN) return;
    if (r == NN) { g_rowptr[NN] = E; return; }
    const int is64 = g_is64;
    int lo = 0, hi = E;
    while (lo < hi) {
        int mid = (lo + hi) >> 1;
        if (load_idx(a_row, mid, is64) < r) lo = mid + 1; else hi = mid;
    }
    g_rowptr[r] = lo;
}

// ---------------- tiled fp32 GEMM: C[M,N] = A[M,K] @ B[K,N] -----------------
// BM=128, BN=64, BK=16, 256 threads, 8x4 microtile.
// Requires: K % 16 == 0, N % 64 == 0 (rows guarded).
#define BM 128
#define BN 64
#define BK 16
#define TM 8
#define TN 4

__global__ __launch_bounds__(256, 4)
void sgemm_kernel(const float* __restrict__ A, const float* __restrict__ B,
                  float* __restrict__ C, int M, int N, int K) {
    __shared__ float As[BK][BM];
    __shared__ float Bs[BK][BN];

    const int tid  = threadIdx.x;
    const int tcol = tid & 15;   // 0..15 -> col group
    const int trow = tid >> 4;   // 0..15 -> row group
    const int rowBase = blockIdx.y * BM;
    const int colBase = blockIdx.x * BN;

    float acc[TM][TN];
    #pragma unroll
    for (int i = 0; i < TM; i++)
        #pragma unroll
        for (int j = 0; j < TN; j++) acc[i][j] = 0.f;

    for (int k0 = 0; k0 < K; k0 += BK) {
        // Load A tile (128x16) transposed into As: 2 float4 per thread
        #pragma unroll
        for (int i = 0; i < 2; i++) {
            int q  = tid + 256 * i;
            int ar = q >> 2;          // 0..127
            int ac = (q & 3) << 2;    // 0,4,8,12
            int grow = rowBase + ar;
            float4 v = make_float4(0.f, 0.f, 0.f, 0.f);
            if (grow < M)
                v = *(const float4*)&A[(size_t)grow * K + k0 + ac];
            As[ac + 0][ar] = v.x;
            As[ac + 1][ar] = v.y;
            As[ac + 2][ar] = v.z;
            As[ac + 3][ar] = v.w;
        }
        // Load B tile (16x64): 1 float4 per thread
        {
            int br = tid >> 4;         // 0..15
            int bc = (tid & 15) << 2;  // 0..60
            *(float4*)&Bs[br][bc] =
                *(const float4*)&B[(size_t)(k0 + br) * N + colBase + bc];
        }
        __syncthreads();

        #pragma unroll
        for (int k = 0; k < BK; k++) {
            float a[TM], b[TN];
            #pragma unroll
            for (int i = 0; i < TM; i++) a[i] = As[k][trow * TM + i];
            #pragma unroll
            for (int j = 0; j < TN; j++) b[j] = Bs[k][tcol * TN + j];
            #pragma unroll
            for (int i = 0; i < TM; i++)
                #pragma unroll
                for (int j = 0; j < TN; j++) acc[i][j] = fmaf(a[i], b[j], acc[i][j]);
        }
        __syncthreads();
    }

    #pragma unroll
    for (int i = 0; i < TM; i++) {
        int r = rowBase + trow * TM + i;
        if (r < M) {
            float4 v = make_float4(acc[i][0], acc[i][1], acc[i][2], acc[i][3]);
            *(float4*)&C[(size_t)r * N + colBase + tcol * TN] = v;
        }
    }
}

// ---------------- SpMM1 (+ ReLU + dropout) : warp per row -------------------
// h[r,:] = relu(sum_e val[e]*xw1[col[e],:]) * mask[r,:] * 2
__global__ __launch_bounds__(256)
void spmm1_kernel(const void* __restrict__ a_col,
                  const float* __restrict__ a_val,
                  const int* __restrict__ drop_mask) {
    int warp = (blockIdx.x * blockDim.x + threadIdx.x) >> 5;
    int lane = threadIdx.x & 31;
    if (warp >= NN) return;
    const int is64 = g_is64;
    int e0 = g_rowptr[warp];
    int e1 = g_rowptr[warp + 1];

    float acc[8];
    #pragma unroll
    for (int j = 0; j < 8; j++) acc[j] = 0.f;

    for (int e = e0; e < e1; e++) {
        int   col = load_idx(a_col, e, is64);
        float v   = __ldg(&a_val[e]);
        const float* src = g_xw1 + (size_t)col * HID;
        #pragma unroll
        for (int j = 0; j < 8; j++)
            acc[j] = fmaf(v, __ldg(&src[j * 32 + lane]), acc[j]);
    }

    const int* mrow = drop_mask + (size_t)warp * HID;
    float*     hrow = g_h       + (size_t)warp * HID;
    #pragma unroll
    for (int j = 0; j < 8; j++) {
        float x = acc[j];
        x = x > 0.f ? x : 0.f;
        x = x * (float)__ldg(&mrow[j * 32 + lane]) * 2.0f;
        hrow[j * 32 + lane] = x;
    }
}

// ---------------- SpMM2 + log_softmax : warp per row ------------------------
__global__ __launch_bounds__(256)
void spmm2_lsm_kernel(const void* __restrict__ a_col,
                      const float* __restrict__ a_val,
                      float* __restrict__ out) {
    int warp = (blockIdx.x * blockDim.x + threadIdx.x) >> 5;
    int lane = threadIdx.x & 31;
    if (warp >= NN) return;
    const int is64 = g_is64;
    int e0 = g_rowptr[warp];
    int e1 = g_rowptr[warp + 1];

    float a0 = 0.f, a1 = 0.f;
    for (int e = e0; e < e1; e++) {
        int   col = load_idx(a_col, e, is64);
        float v   = __ldg(&a_val[e]);
        const float* src = g_hw2 + (size_t)col * OUT_F;
        a0 = fmaf(v, __ldg(&src[lane]),      a0);
        a1 = fmaf(v, __ldg(&src[32 + lane]), a1);
    }

    // log_softmax over the 64 values spread 2-per-lane across the warp
    float m = fmaxf(a0, a1);
    #pragma unroll
    for (int off = 16; off > 0; off >>= 1)
        m = fmaxf(m, __shfl_xor_sync(0xFFFFFFFFu, m, off));
    float s = expf(a0 - m) + expf(a1 - m);
    #pragma unroll
    for (int off = 16; off > 0; off >>= 1)
        s += __shfl_xor_sync(0xFFFFFFFFu, s, off);
    float ls = logf(s) + m;

    out[(size_t)warp * OUT_F + lane]      = a0 - ls;
    out[(size_t)warp * OUT_F + 32 + lane] = a1 - ls;
}

// ---------------- launch ----------------------------------------------------
extern "C" void kernel_launch(void* const* d_in, const int* in_sizes, int n_in,
                              void* d_out, int out_size) {
    const float* X     = (const float*)d_in[0];
    const float* W1    = (const float*)d_in[1];
    const float* W2    = (const float*)d_in[2];
    const void*  a_row = d_in[3];
    const void*  a_col = d_in[4];
    const float* a_val = (const float*)d_in[5];
    const int*   dmask = (const int*)d_in[6];
    float*       out   = (float*)d_out;

    const int E = in_sizes[5];  // a_val element count

    float *p_xw1, *p_h, *p_hw2;
    cudaGetSymbolAddress((void**)&p_xw1, g_xw1);
    cudaGetSymbolAddress((void**)&p_h,   g_h);
    cudaGetSymbolAddress((void**)&p_hw2, g_hw2);

    // 0) detect index dtype (int32 vs int64)
    detect_idx_kernel<<<1, 32>>>(a_col, E);

    // 1) row pointers from sorted a_row
    build_rowptr_kernel<<<(NN + 1 + 255) / 256, 256>>>(a_row, E);

    // 2) GEMM1: xw1 = X @ W1   [50000,512] x [512,256]
    {
        dim3 grid(HID / BN, (NN + BM - 1) / BM);
        sgemm_kernel<<<grid, 256>>>(X, W1, p_xw1, NN, HID, IN_F);
    }

    // 3) SpMM1 + relu + dropout -> h
    {
        int warps_per_block = 256 / 32;
        int blocks = (NN + warps_per_block - 1) / warps_per_block;
        spmm1_kernel<<<blocks, 256>>>(a_col, a_val, dmask);
    }

    // 4) GEMM2: hw2 = h @ W2   [50000,256] x [256,64]
    {
        dim3 grid(OUT_F / BN, (NN + BM - 1) / BM);
        sgemm_kernel<<<grid, 256>>>(p_h, W2, p_hw2, NN, OUT_F, HID);
    }

    // 5) SpMM2 + log_softmax -> out
    {
        int warps_per_block = 256 / 32;
        int blocks = (NN + warps_per_block - 1) / warps_per_block;
        spmm2_lsm_kernel<<<blocks, 256>>>(a_col, a_val, out);
    }
}

// round 4
// speedup vs baseline: 1.5886x; 1.5886x over previous
#include <cuda_runtime.h>
#include <cuda_bf16.h>
#include <math.h>
#include <stdint.h>

// Problem constants
#define NN    50000
#define EE    800000
#define IN_F  512
#define HID   256
#define OUT_F 64

// ---------------- scratch (static device globals; no allocs) ----------------
__device__ float g_xw1[(size_t)NN * HID];   // X @ W1
__device__ float g_h  [(size_t)NN * HID];   // relu+dropout(SpMM1)
__device__ float g_hw2[(size_t)NN * OUT_F]; // h @ W2
__device__ int   g_rowptr[NN + 1];
__device__ int   g_is64;                    // 1 if indices are int64, 0 if int32
__device__ __nv_bfloat16 g_x_hi[(size_t)NN * IN_F];    // X split hi (row-major)
__device__ __nv_bfloat16 g_x_lo[(size_t)NN * IN_F];    // X split lo
__device__ __nv_bfloat16 g_w1t_hi[(size_t)HID * IN_F]; // W1^T hi  [256,512] K-major
__device__ __nv_bfloat16 g_w1t_lo[(size_t)HID * IN_F]; // W1^T lo

// ======================= PTX helpers ========================================
__device__ __forceinline__ uint32_t smem_u32(const void* p) {
    uint32_t a;
    asm("{ .reg .u64 t; cvta.to.shared.u64 t, %1; cvt.u32.u64 %0, t; }"
        : "=r"(a) : "l"(p));
    return a;
}
__device__ __forceinline__ void cpa16(uint32_t dst, const void* src) {
    asm volatile("cp.async.cg.shared.global [%0], [%1], 16;"
                 :: "r"(dst), "l"(src) : "memory");
}
#define CP_COMMIT()  asm volatile("cp.async.commit_group;" ::: "memory")
#define CP_WAIT_1()  asm volatile("cp.async.wait_group 1;" ::: "memory")
#define CP_WAIT_0()  asm volatile("cp.async.wait_group 0;" ::: "memory")

__device__ __forceinline__ void ldsm_x4(uint32_t& r0, uint32_t& r1,
                                        uint32_t& r2, uint32_t& r3, uint32_t addr) {
    asm volatile("ldmatrix.sync.aligned.m8n8.x4.shared.b16 {%0,%1,%2,%3}, [%4];"
                 : "=r"(r0), "=r"(r1), "=r"(r2), "=r"(r3) : "r"(addr));
}
__device__ __forceinline__ void mma_bf16(float* c, const uint32_t* a, const uint32_t* b) {
    asm volatile(
        "mma.sync.aligned.m16n8k16.row.col.f32.bf16.bf16.f32 "
        "{%0,%1,%2,%3}, {%4,%5,%6,%7}, {%8,%9}, {%0,%1,%2,%3};"
        : "+f"(c[0]), "+f"(c[1]), "+f"(c[2]), "+f"(c[3])
        : "r"(a[0]), "r"(a[1]), "r"(a[2]), "r"(a[3]), "r"(b[0]), "r"(b[1]));
}

__device__ __forceinline__ uint32_t bf2_pack(float a, float b) {
    __nv_bfloat162 t = __floats2bfloat162_rn(a, b);
    return *reinterpret_cast<uint32_t*>(&t);
}
__device__ __forceinline__ float bf_round(float x) {
    return __bfloat162float(__float2bfloat16_rn(x));
}

// ---------------- index dtype detection (int64 vs int32) --------------------
__global__ void detect_idx_kernel(const void* __restrict__ a_col_raw, int E) {
    if (threadIdx.x != 0 || blockIdx.x != 0) return;
    const long long* p = (const long long*)a_col_raw;
    int ok = 1;
    for (int i = 0; i < 16; i++) {
        long long v = p[i];
        if (v < 0 || v >= NN) { ok = 0; break; }
    }
    if (ok) {
        for (int i = 0; i < 16; i++) {
            long long v = p[E / 2 + i];
            if (v < 0 || v >= NN) { ok = 0; break; }
        }
    }
    g_is64 = ok;
}
__device__ __forceinline__ int load_idx(const void* p, int i, int is64) {
    if (is64) return (int)((const long long*)p)[i];
    return ((const int*)p)[i];
}

// ---------------- rowptr: lower_bound per row over sorted a_row -------------
__global__ void build_rowptr_kernel(const void* __restrict__ a_row, int E) {
    int r = blockIdx.x * blockDim.x + threadIdx.x;
    if (r > NN) return;
    if (r == NN) { g_rowptr[NN] = E; return; }
    const int is64 = g_is64;
    int lo = 0, hi = E;
    while (lo < hi) {
        int mid = (lo + hi) >> 1;
        if (load_idx(a_row, mid, is64) < r) lo = mid + 1; else hi = mid;
    }
    g_rowptr[r] = lo;
}

// ---------------- prep: X -> bf16 hi/lo (flat) ------------------------------
__global__ void prep_x_kernel(const float* __restrict__ X) {
    size_t idx4 = (size_t)blockIdx.x * blockDim.x + threadIdx.x;
    size_t base = idx4 * 4;
    if (base >= (size_t)NN * IN_F) return;
    float4 v = *(const float4*)(X + base);
    float h0 = bf_round(v.x), h1 = bf_round(v.y);
    float h2 = bf_round(v.z), h3 = bf_round(v.w);
    uint2 hi = make_uint2(bf2_pack(v.x, v.y), bf2_pack(v.z, v.w));
    uint2 lo = make_uint2(bf2_pack(v.x - h0, v.y - h1), bf2_pack(v.z - h2, v.w - h3));
    *(uint2*)(g_x_hi + base) = hi;
    *(uint2*)(g_x_lo + base) = lo;
}

// ---------------- prep: W1^T bf16 hi/lo -------------------------------------
__global__ void prep_w1t_kernel(const float* __restrict__ W1) {
    int idx = blockIdx.x * blockDim.x + threadIdx.x;
    if (idx >= IN_F * HID) return;
    int n = idx >> 9;        // 0..255
    int k = idx & 511;       // 0..511
    float v = W1[(size_t)k * HID + n];
    __nv_bfloat16 h = __float2bfloat16_rn(v);
    g_w1t_hi[idx] = h;
    g_w1t_lo[idx] = __float2bfloat16_rn(v - __bfloat162float(h));
}

// ---------------- GEMM1 via mma.sync bf16 (3-term split) --------------------
// CTA tile 128(M) x 128(N), K chunk 32, double-buffered cp.async.
// 8 warps: warp_m = wid&3 (32 rows each), warp_n = wid>>2 (64 cols each).
#define ROWB    80          // smem row pitch (64B data + 16B pad; ldmatrix conflict-free)
#define ST_A_HI 0
#define ST_A_LO 10240
#define ST_B_HI 20480
#define ST_B_LO 30720
#define STAGE_SZ 40960
#define GSMEM_TOTAL (2 * STAGE_SZ)   // 81920

__global__ void __launch_bounds__(256)
gemm1_mma_kernel(float* __restrict__ out) {
    extern __shared__ char smem[];
    const uint32_t sm0 = smem_u32(smem);
    const int tid = threadIdx.x;
    const int wid = tid >> 5, lane = tid & 31;
    const int warp_m = wid & 3, warp_n = wid >> 2;
    const int rowBase = blockIdx.x * 128;
    const int colBase = blockIdx.y * 128;

    float acc[2][8][4];
    #pragma unroll
    for (int i = 0; i < 2; i++)
        #pragma unroll
        for (int j = 0; j < 8; j++)
            #pragma unroll
            for (int t = 0; t < 4; t++) acc[i][j][t] = 0.f;

    // per-thread load mapping: 2 chunks per region
    int c0 = tid, c1 = tid + 256;

    auto load_stage = [&](int s, int kc) {
        int k0 = kc * 32;
        uint32_t sb = sm0 + s * STAGE_SZ;
        #pragma unroll
        for (int i = 0; i < 2; i++) {
            int c = i ? c1 : c0;          // 0..511
            int row = c >> 2;             // 0..127
            int q   = c & 3;              // 16B sub-chunk
            int row_g = rowBase + row; if (row_g >= NN) row_g = NN - 1;
            int n_g   = colBase + row;
            const __nv_bfloat16* axh = g_x_hi  + (size_t)row_g * IN_F + k0 + q * 8;
            const __nv_bfloat16* axl = g_x_lo  + (size_t)row_g * IN_F + k0 + q * 8;
            const __nv_bfloat16* bxh = g_w1t_hi + (size_t)n_g  * IN_F + k0 + q * 8;
            const __nv_bfloat16* bxl = g_w1t_lo + (size_t)n_g  * IN_F + k0 + q * 8;
            uint32_t o = row * ROWB + q * 16;
            cpa16(sb + ST_A_HI + o, axh);
            cpa16(sb + ST_A_LO + o, axl);
            cpa16(sb + ST_B_HI + o, bxh);
            cpa16(sb + ST_B_LO + o, bxl);
        }
    };

    const int lq = lane >> 3;   // quadrant 0..3
    const int lr = lane & 7;    // row within quadrant

    auto compute_stage = [&](int s) {
        uint32_t sb = sm0 + s * STAGE_SZ;
        #pragma unroll
        for (int ks = 0; ks < 2; ks++) {
            // A fragments (hi & lo) for 2 m16 blocks
            uint32_t ahi[2][4], alo[2][4];
            #pragma unroll
            for (int mb = 0; mb < 2; mb++) {
                int row = warp_m * 32 + mb * 16 + (lq & 1) * 8 + lr;
                int kb  = ks * 32 + (lq >> 1) * 16;
                uint32_t o = row * ROWB + kb;
                ldsm_x4(ahi[mb][0], ahi[mb][1], ahi[mb][2], ahi[mb][3], sb + ST_A_HI + o);
                ldsm_x4(alo[mb][0], alo[mb][1], alo[mb][2], alo[mb][3], sb + ST_A_LO + o);
            }
            // B fragments (hi & lo) for 8 n8 blocks (4 x4-loads each)
            uint32_t bhi[8][2], blo[8][2];
            #pragma unroll
            for (int g = 0; g < 4; g++) {
                int row = warp_n * 64 + g * 16 + (lq >> 1) * 8 + lr;
                int kb  = ks * 32 + (lq & 1) * 16;
                uint32_t o = row * ROWB + kb;
                ldsm_x4(bhi[2*g][0], bhi[2*g][1], bhi[2*g+1][0], bhi[2*g+1][1],
                        sb + ST_B_HI + o);
                ldsm_x4(blo[2*g][0], blo[2*g][1], blo[2*g+1][0], blo[2*g+1][1],
                        sb + ST_B_LO + o);
            }
            #pragma unroll
            for (int mb = 0; mb < 2; mb++)
                #pragma unroll
                for (int nb = 0; nb < 8; nb++) {
                    mma_bf16(acc[mb][nb], ahi[mb], bhi[nb]);
                    mma_bf16(acc[mb][nb], ahi[mb], blo[nb]);
                    mma_bf16(acc[mb][nb], alo[mb], bhi[nb]);
                }
        }
    };

    load_stage(0, 0);
    CP_COMMIT();
    for (int kc = 0; kc < 16; kc++) {
        if (kc < 15) {
            load_stage((kc + 1) & 1, kc + 1);
            CP_COMMIT();
            CP_WAIT_1();
        } else {
            CP_WAIT_0();
        }
        __syncthreads();
        compute_stage(kc & 1);
        __syncthreads();
    }

    // Epilogue: fp32 accumulators -> g_xw1
    const int gid = lane >> 2, tg = lane & 3;
    #pragma unroll
    for (int mb = 0; mb < 2; mb++) {
        int r0 = rowBase + warp_m * 32 + mb * 16 + gid;
        int r1 = r0 + 8;
        #pragma unroll
        for (int nb = 0; nb < 8; nb++) {
            int col = colBase + warp_n * 64 + nb * 8 + tg * 2;
            if (r0 < NN)
                *(float2*)&out[(size_t)r0 * HID + col] =
                    make_float2(acc[mb][nb][0], acc[mb][nb][1]);
            if (r1 < NN)
                *(float2*)&out[(size_t)r1 * HID + col] =
                    make_float2(acc[mb][nb][2], acc[mb][nb][3]);
        }
    }
}

// ---------------- tiled fp32 GEMM (GEMM2) -----------------------------------
#define BM 128
#define BN 64
#define BK 16
#define TM 8
#define TN 4

__global__ __launch_bounds__(256, 4)
void sgemm_kernel(const float* __restrict__ A, const float* __restrict__ B,
                  float* __restrict__ C, int M, int N, int K) {
    __shared__ float As[BK][BM];
    __shared__ float Bs[BK][BN];

    const int tid  = threadIdx.x;
    const int tcol = tid & 15;
    const int trow = tid >> 4;
    const int rowBase = blockIdx.y * BM;
    const int colBase = blockIdx.x * BN;

    float acc[TM][TN];
    #pragma unroll
    for (int i = 0; i < TM; i++)
        #pragma unroll
        for (int j = 0; j < TN; j++) acc[i][j] = 0.f;

    for (int k0 = 0; k0 < K; k0 += BK) {
        #pragma unroll
        for (int i = 0; i < 2; i++) {
            int q  = tid + 256 * i;
            int ar = q >> 2;
            int ac = (q & 3) << 2;
            int grow = rowBase + ar;
            float4 v = make_float4(0.f, 0.f, 0.f, 0.f);
            if (grow < M)
                v = *(const float4*)&A[(size_t)grow * K + k0 + ac];
            As[ac + 0][ar] = v.x;
            As[ac + 1][ar] = v.y;
            As[ac + 2][ar] = v.z;
            As[ac + 3][ar] = v.w;
        }
        {
            int br = tid >> 4;
            int bc = (tid & 15) << 2;
            *(float4*)&Bs[br][bc] =
                *(const float4*)&B[(size_t)(k0 + br) * N + colBase + bc];
        }
        __syncthreads();

        #pragma unroll
        for (int k = 0; k < BK; k++) {
            float a[TM], b[TN];
            #pragma unroll
            for (int i = 0; i < TM; i++) a[i] = As[k][trow * TM + i];
            #pragma unroll
            for (int j = 0; j < TN; j++) b[j] = Bs[k][tcol * TN + j];
            #pragma unroll
            for (int i = 0; i < TM; i++)
                #pragma unroll
                for (int j = 0; j < TN; j++) acc[i][j] = fmaf(a[i], b[j], acc[i][j]);
        }
        __syncthreads();
    }

    #pragma unroll
    for (int i = 0; i < TM; i++) {
        int r = rowBase + trow * TM + i;
        if (r < M) {
            float4 v = make_float4(acc[i][0], acc[i][1], acc[i][2], acc[i][3]);
            *(float4*)&C[(size_t)r * N + colBase + tcol * TN] = v;
        }
    }
}

// ---------------- SpMM1 (+ ReLU + dropout) : warp per row, float4 -----------
__global__ __launch_bounds__(256)
void spmm1_kernel(const void* __restrict__ a_col,
                  const float* __restrict__ a_val,
                  const int* __restrict__ drop_mask) {
    int warp = (blockIdx.x * blockDim.x + threadIdx.x) >> 5;
    int lane = threadIdx.x & 31;
    if (warp >= NN) return;
    const int is64 = g_is64;
    int e0 = g_rowptr[warp];
    int e1 = g_rowptr[warp + 1];

    float4 acc0 = make_float4(0.f, 0.f, 0.f, 0.f);
    float4 acc1 = make_float4(0.f, 0.f, 0.f, 0.f);

    for (int e = e0; e < e1; e++) {
        int   col = load_idx(a_col, e, is64);
        float v   = __ldg(&a_val[e]);
        const float4* src = (const float4*)(g_xw1 + (size_t)col * HID) + lane * 2;
        float4 x0 = __ldg(src);
        float4 x1 = __ldg(src + 1);
        acc0.x = fmaf(v, x0.x, acc0.x); acc0.y = fmaf(v, x0.y, acc0.y);
        acc0.z = fmaf(v, x0.z, acc0.z); acc0.w = fmaf(v, x0.w, acc0.w);
        acc1.x = fmaf(v, x1.x, acc1.x); acc1.y = fmaf(v, x1.y, acc1.y);
        acc1.z = fmaf(v, x1.z, acc1.z); acc1.w = fmaf(v, x1.w, acc1.w);
    }

    const int4* mrow = (const int4*)(drop_mask + (size_t)warp * HID) + lane * 2;
    int4 m0 = __ldg(mrow);
    int4 m1 = __ldg(mrow + 1);

    float4 r0, r1;
    r0.x = fmaxf(acc0.x, 0.f) * (float)m0.x * 2.0f;
    r0.y = fmaxf(acc0.y, 0.f) * (float)m0.y * 2.0f;
    r0.z = fmaxf(acc0.z, 0.f) * (float)m0.z * 2.0f;
    r0.w = fmaxf(acc0.w, 0.f) * (float)m0.w * 2.0f;
    r1.x = fmaxf(acc1.x, 0.f) * (float)m1.x * 2.0f;
    r1.y = fmaxf(acc1.y, 0.f) * (float)m1.y * 2.0f;
    r1.z = fmaxf(acc1.z, 0.f) * (float)m1.z * 2.0f;
    r1.w = fmaxf(acc1.w, 0.f) * (float)m1.w * 2.0f;

    float4* hrow = (float4*)(g_h + (size_t)warp * HID) + lane * 2;
    hrow[0] = r0;
    hrow[1] = r1;
}

// ---------------- SpMM2 + log_softmax : warp per row ------------------------
__global__ __launch_bounds__(256)
void spmm2_lsm_kernel(const void* __restrict__ a_col,
                      const float* __restrict__ a_val,
                      float* __restrict__ out) {
    int warp = (blockIdx.x * blockDim.x + threadIdx.x) >> 5;
    int lane = threadIdx.x & 31;
    if (warp >= NN) return;
    const int is64 = g_is64;
    int e0 = g_rowptr[warp];
    int e1 = g_rowptr[warp + 1];

    float a0 = 0.f, a1 = 0.f;
    for (int e = e0; e < e1; e++) {
        int   col = load_idx(a_col, e, is64);
        float v   = __ldg(&a_val[e]);
        const float* src = g_hw2 + (size_t)col * OUT_F;
        a0 = fmaf(v, __ldg(&src[lane]),      a0);
        a1 = fmaf(v, __ldg(&src[32 + lane]), a1);
    }

    float m = fmaxf(a0, a1);
    #pragma unroll
    for (int off = 16; off > 0; off >>= 1)
        m = fmaxf(m, __shfl_xor_sync(0xFFFFFFFFu, m, off));
    float s = expf(a0 - m) + expf(a1 - m);
    #pragma unroll
    for (int off = 16; off > 0; off >>= 1)
        s += __shfl_xor_sync(0xFFFFFFFFu, s, off);
    float ls = logf(s) + m;

    out[(size_t)warp * OUT_F + lane]      = a0 - ls;
    out[(size_t)warp * OUT_F + 32 + lane] = a1 - ls;
}

// ---------------- launch ----------------------------------------------------
extern "C" void kernel_launch(void* const* d_in, const int* in_sizes, int n_in,
                              void* d_out, int out_size) {
    const float* X     = (const float*)d_in[0];
    const float* W1    = (const float*)d_in[1];
    const float* W2    = (const float*)d_in[2];
    const void*  a_row = d_in[3];
    const void*  a_col = d_in[4];
    const float* a_val = (const float*)d_in[5];
    const int*   dmask = (const int*)d_in[6];
    float*       out   = (float*)d_out;

    const int E = in_sizes[5];

    float *p_xw1, *p_h, *p_hw2;
    cudaGetSymbolAddress((void**)&p_xw1, g_xw1);
    cudaGetSymbolAddress((void**)&p_h,   g_h);
    cudaGetSymbolAddress((void**)&p_hw2, g_hw2);

    static int smem_set = 0;
    if (!smem_set) {
        cudaFuncSetAttribute(gemm1_mma_kernel,
                             cudaFuncAttributeMaxDynamicSharedMemorySize, GSMEM_TOTAL);
        smem_set = 1;
    }

    // 0) detect index dtype (int32 vs int64)
    detect_idx_kernel<<<1, 32>>>(a_col, E);

    // 1) independent preps
    build_rowptr_kernel<<<(NN + 1 + 255) / 256, 256>>>(a_row, E);
    prep_x_kernel<<<((NN * IN_F / 4) + 255) / 256, 256>>>(X);
    prep_w1t_kernel<<<(IN_F * HID + 255) / 256, 256>>>(W1);

    // 2) GEMM1 on tensor cores: xw1 = X @ W1
    {
        dim3 grid((NN + 127) / 128, HID / 128);
        gemm1_mma_kernel<<<grid, 256, GSMEM_TOTAL>>>(p_xw1);
    }

    // 3) SpMM1 + relu + dropout -> h
    spmm1_kernel<<<(NN * 32 + 255) / 256, 256>>>(a_col, a_val, dmask);

    // 4) GEMM2: hw2 = h @ W2
    {
        dim3 grid(OUT_F / BN, (NN + BM - 1) / BM);
        sgemm_kernel<<<grid, 256>>>(p_h, W2, p_hw2, NN, OUT_F, HID);
    }

    // 5) SpMM2 + log_softmax -> out
    spmm2_lsm_kernel<<<(NN * 32 + 255) / 256, 256>>>(a_col, a_val, out);
}

// round 5
// speedup vs baseline: 1.7619x; 1.1091x over previous
#include <cuda_runtime.h>
#include <cuda_bf16.h>
#include <math.h>
#include <stdint.h>

// Problem constants
#define NN    50000
#define EE    800000
#define IN_F  512
#define HID   256
#define OUT_F 64

// ---------------- scratch (static device globals; no allocs) ----------------
__device__ float g_xw1[(size_t)NN * HID];   // X @ W1
__device__ float g_hw2[(size_t)NN * OUT_F]; // h @ W2
__device__ int   g_rowptr[NN + 1];
__device__ int   g_is64;
__device__ __nv_bfloat16 g_x_hi[(size_t)NN * IN_F];    // X split hi (row-major)
__device__ __nv_bfloat16 g_x_lo[(size_t)NN * IN_F];    // X split lo
__device__ __nv_bfloat16 g_w1t_hi[(size_t)HID * IN_F]; // W1^T hi  [256,512]
__device__ __nv_bfloat16 g_w1t_lo[(size_t)HID * IN_F]; // W1^T lo
__device__ __nv_bfloat16 g_h_hi[(size_t)NN * HID];     // h split hi [50000,256]
__device__ __nv_bfloat16 g_h_lo[(size_t)NN * HID];     // h split lo
__device__ __nv_bfloat16 g_w2t_hi[(size_t)OUT_F * HID]; // W2^T hi [64,256]
__device__ __nv_bfloat16 g_w2t_lo[(size_t)OUT_F * HID]; // W2^T lo

// ======================= PTX helpers ========================================
__device__ __forceinline__ uint32_t smem_u32(const void* p) {
    uint32_t a;
    asm("{ .reg .u64 t; cvta.to.shared.u64 t, %1; cvt.u32.u64 %0, t; }"
        : "=r"(a) : "l"(p));
    return a;
}
__device__ __forceinline__ void cpa16(uint32_t dst, const void* src) {
    asm volatile("cp.async.cg.shared.global [%0], [%1], 16;"
                 :: "r"(dst), "l"(src) : "memory");
}
#define CP_COMMIT()  asm volatile("cp.async.commit_group;" ::: "memory")
#define CP_WAIT_1()  asm volatile("cp.async.wait_group 1;" ::: "memory")
#define CP_WAIT_0()  asm volatile("cp.async.wait_group 0;" ::: "memory")

__device__ __forceinline__ void ldsm_x4(uint32_t& r0, uint32_t& r1,
                                        uint32_t& r2, uint32_t& r3, uint32_t addr) {
    asm volatile("ldmatrix.sync.aligned.m8n8.x4.shared.b16 {%0,%1,%2,%3}, [%4];"
                 : "=r"(r0), "=r"(r1), "=r"(r2), "=r"(r3) : "r"(addr));
}
__device__ __forceinline__ void mma_bf16(float* c, const uint32_t* a, const uint32_t* b) {
    asm volatile(
        "mma.sync.aligned.m16n8k16.row.col.f32.bf16.bf16.f32 "
        "{%0,%1,%2,%3}, {%4,%5,%6,%7}, {%8,%9}, {%0,%1,%2,%3};"
        : "+f"(c[0]), "+f"(c[1]), "+f"(c[2]), "+f"(c[3])
        : "r"(a[0]), "r"(a[1]), "r"(a[2]), "r"(a[3]), "r"(b[0]), "r"(b[1]));
}

__device__ __forceinline__ uint32_t bf2_pack(float a, float b) {
    __nv_bfloat162 t = __floats2bfloat162_rn(a, b);
    return *reinterpret_cast<uint32_t*>(&t);
}
__device__ __forceinline__ float bf_round(float x) {
    return __bfloat162float(__float2bfloat16_rn(x));
}

// ---------------- index dtype detection (int64 vs int32) --------------------
__global__ void detect_idx_kernel(const void* __restrict__ a_col_raw, int E) {
    if (threadIdx.x != 0 || blockIdx.x != 0) return;
    const long long* p = (const long long*)a_col_raw;
    int ok = 1;
    for (int i = 0; i < 16; i++) {
        long long v = p[i];
        if (v < 0 || v >= NN) { ok = 0; break; }
    }
    if (ok) {
        for (int i = 0; i < 16; i++) {
            long long v = p[E / 2 + i];
            if (v < 0 || v >= NN) { ok = 0; break; }
        }
    }
    g_is64 = ok;
}
__device__ __forceinline__ int load_idx(const void* p, int i, int is64) {
    if (is64) return (int)((const long long*)p)[i];
    return ((const int*)p)[i];
}

// ---------------- rowptr ----------------------------------------------------
__global__ void build_rowptr_kernel(const void* __restrict__ a_row, int E) {
    int r = blockIdx.x * blockDim.x + threadIdx.x;
    if (r > NN) return;
    if (r == NN) { g_rowptr[NN] = E; return; }
    const int is64 = g_is64;
    int lo = 0, hi = E;
    while (lo < hi) {
        int mid = (lo + hi) >> 1;
        if (load_idx(a_row, mid, is64) < r) lo = mid + 1; else hi = mid;
    }
    g_rowptr[r] = lo;
}

// ---------------- preps -----------------------------------------------------
__global__ void prep_x_kernel(const float* __restrict__ X) {
    size_t base = ((size_t)blockIdx.x * blockDim.x + threadIdx.x) * 4;
    if (base >= (size_t)NN * IN_F) return;
    float4 v = *(const float4*)(X + base);
    float h0 = bf_round(v.x), h1 = bf_round(v.y);
    float h2 = bf_round(v.z), h3 = bf_round(v.w);
    *(uint2*)(g_x_hi + base) = make_uint2(bf2_pack(v.x, v.y), bf2_pack(v.z, v.w));
    *(uint2*)(g_x_lo + base) = make_uint2(bf2_pack(v.x - h0, v.y - h1),
                                          bf2_pack(v.z - h2, v.w - h3));
}

__global__ void prep_w1t_kernel(const float* __restrict__ W1) {
    int idx = blockIdx.x * blockDim.x + threadIdx.x;
    if (idx >= IN_F * HID) return;
    int n = idx >> 9, k = idx & 511;
    float v = W1[(size_t)k * HID + n];
    __nv_bfloat16 h = __float2bfloat16_rn(v);
    g_w1t_hi[idx] = h;
    g_w1t_lo[idx] = __float2bfloat16_rn(v - __bfloat162float(h));
}

__global__ void prep_w2t_kernel(const float* __restrict__ W2) {
    int idx = blockIdx.x * blockDim.x + threadIdx.x;
    if (idx >= HID * OUT_F) return;
    int n = idx >> 8, k = idx & 255;   // n: 0..63, k: 0..255
    float v = W2[(size_t)k * OUT_F + n];
    __nv_bfloat16 h = __float2bfloat16_rn(v);
    g_w2t_hi[idx] = h;
    g_w2t_lo[idx] = __float2bfloat16_rn(v - __bfloat162float(h));
}

// ---------------- GEMM1 via mma.sync bf16 (3-term split) --------------------
#define ROWB    80
#define ST_A_HI 0
#define ST_A_LO 10240
#define ST_B_HI 20480
#define ST_B_LO 30720
#define STAGE_SZ 40960
#define GSMEM_TOTAL (2 * STAGE_SZ)   // 81920

__global__ void __launch_bounds__(256)
gemm1_mma_kernel(float* __restrict__ out) {
    extern __shared__ char smem[];
    const uint32_t sm0 = smem_u32(smem);
    const int tid = threadIdx.x;
    const int wid = tid >> 5, lane = tid & 31;
    const int warp_m = wid & 3, warp_n = wid >> 2;
    const int rowBase = blockIdx.x * 128;
    const int colBase = blockIdx.y * 128;

    float acc[2][8][4];
    #pragma unroll
    for (int i = 0; i < 2; i++)
        #pragma unroll
        for (int j = 0; j < 8; j++)
            #pragma unroll
            for (int t = 0; t < 4; t++) acc[i][j][t] = 0.f;

    auto load_stage = [&](int s, int kc) {
        int k0 = kc * 32;
        uint32_t sb = sm0 + s * STAGE_SZ;
        #pragma unroll
        for (int i = 0; i < 2; i++) {
            int c = tid + 256 * i;
            int row = c >> 2, q = c & 3;
            int row_g = rowBase + row; if (row_g >= NN) row_g = NN - 1;
            int n_g   = colBase + row;
            uint32_t o = row * ROWB + q * 16;
            cpa16(sb + ST_A_HI + o, g_x_hi  + (size_t)row_g * IN_F + k0 + q * 8);
            cpa16(sb + ST_A_LO + o, g_x_lo  + (size_t)row_g * IN_F + k0 + q * 8);
            cpa16(sb + ST_B_HI + o, g_w1t_hi + (size_t)n_g  * IN_F + k0 + q * 8);
            cpa16(sb + ST_B_LO + o, g_w1t_lo + (size_t)n_g  * IN_F + k0 + q * 8);
        }
    };

    const int lq = lane >> 3, lr = lane & 7;

    auto compute_stage = [&](int s) {
        uint32_t sb = sm0 + s * STAGE_SZ;
        #pragma unroll
        for (int ks = 0; ks < 2; ks++) {
            uint32_t ahi[2][4], alo[2][4];
            #pragma unroll
            for (int mb = 0; mb < 2; mb++) {
                int row = warp_m * 32 + mb * 16 + (lq & 1) * 8 + lr;
                int kb  = ks * 32 + (lq >> 1) * 16;
                uint32_t o = row * ROWB + kb;
                ldsm_x4(ahi[mb][0], ahi[mb][1], ahi[mb][2], ahi[mb][3], sb + ST_A_HI + o);
                ldsm_x4(alo[mb][0], alo[mb][1], alo[mb][2], alo[mb][3], sb + ST_A_LO + o);
            }
            uint32_t bhi[8][2], blo[8][2];
            #pragma unroll
            for (int g = 0; g < 4; g++) {
                int row = warp_n * 64 + g * 16 + (lq >> 1) * 8 + lr;
                int kb  = ks * 32 + (lq & 1) * 16;
                uint32_t o = row * ROWB + kb;
                ldsm_x4(bhi[2*g][0], bhi[2*g][1], bhi[2*g+1][0], bhi[2*g+1][1],
                        sb + ST_B_HI + o);
                ldsm_x4(blo[2*g][0], blo[2*g][1], blo[2*g+1][0], blo[2*g+1][1],
                        sb + ST_B_LO + o);
            }
            #pragma unroll
            for (int mb = 0; mb < 2; mb++)
                #pragma unroll
                for (int nb = 0; nb < 8; nb++) {
                    mma_bf16(acc[mb][nb], ahi[mb], bhi[nb]);
                    mma_bf16(acc[mb][nb], ahi[mb], blo[nb]);
                    mma_bf16(acc[mb][nb], alo[mb], bhi[nb]);
                }
        }
    };

    load_stage(0, 0);
    CP_COMMIT();
    for (int kc = 0; kc < 16; kc++) {
        if (kc < 15) {
            load_stage((kc + 1) & 1, kc + 1);
            CP_COMMIT();
            CP_WAIT_1();
        } else {
            CP_WAIT_0();
        }
        __syncthreads();
        compute_stage(kc & 1);
        __syncthreads();
    }

    const int gid = lane >> 2, tg = lane & 3;
    #pragma unroll
    for (int mb = 0; mb < 2; mb++) {
        int r0 = rowBase + warp_m * 32 + mb * 16 + gid;
        int r1 = r0 + 8;
        #pragma unroll
        for (int nb = 0; nb < 8; nb++) {
            int col = colBase + warp_n * 64 + nb * 8 + tg * 2;
            if (r0 < NN)
                *(float2*)&out[(size_t)r0 * HID + col] =
                    make_float2(acc[mb][nb][0], acc[mb][nb][1]);
            if (r1 < NN)
                *(float2*)&out[(size_t)r1 * HID + col] =
                    make_float2(acc[mb][nb][2], acc[mb][nb][3]);
        }
    }
}

// ---------------- GEMM2 via mma.sync bf16 (3-term split) --------------------
// C[50000,64] = h[50000,256] @ W2[256,64]; CTA 128x64, K chunk 32, 8 chunks.
#define S2_A_HI 0
#define S2_A_LO 10240
#define S2_B_HI 20480
#define S2_B_LO 25600
#define STG2    30720
#define G2SMEM_TOTAL (2 * STG2)   // 61440

__global__ void __launch_bounds__(256)
gemm2_mma_kernel(float* __restrict__ out) {
    extern __shared__ char smem[];
    const uint32_t sm0 = smem_u32(smem);
    const int tid = threadIdx.x;
    const int wid = tid >> 5, lane = tid & 31;
    const int warp_m = wid & 3, warp_n = wid >> 2;   // warp_n 0..1, 32 cols each
    const int rowBase = blockIdx.x * 128;

    float acc[2][4][4];
    #pragma unroll
    for (int i = 0; i < 2; i++)
        #pragma unroll
        for (int j = 0; j < 4; j++)
            #pragma unroll
            for (int t = 0; t < 4; t++) acc[i][j][t] = 0.f;

    auto load_stage = [&](int s, int kc) {
        int k0 = kc * 32;
        uint32_t sb = sm0 + s * STG2;
        #pragma unroll
        for (int i = 0; i < 2; i++) {
            int c = tid + 256 * i;       // 0..511
            int row = c >> 2, q = c & 3;
            int rg = rowBase + row; if (rg >= NN) rg = NN - 1;
            uint32_t o = row * ROWB + q * 16;
            cpa16(sb + S2_A_HI + o, g_h_hi + (size_t)rg * HID + k0 + q * 8);
            cpa16(sb + S2_A_LO + o, g_h_lo + (size_t)rg * HID + k0 + q * 8);
        }
        {
            int row = tid >> 2, q = tid & 3;  // row 0..63
            uint32_t o = row * ROWB + q * 16;
            cpa16(sb + S2_B_HI + o, g_w2t_hi + (size_t)row * HID + k0 + q * 8);
            cpa16(sb + S2_B_LO + o, g_w2t_lo + (size_t)row * HID + k0 + q * 8);
        }
    };

    const int lq = lane >> 3, lr = lane & 7;

    auto compute_stage = [&](int s) {
        uint32_t sb = sm0 + s * STG2;
        #pragma unroll
        for (int ks = 0; ks < 2; ks++) {
            uint32_t ahi[2][4], alo[2][4];
            #pragma unroll
            for (int mb = 0; mb < 2; mb++) {
                int row = warp_m * 32 + mb * 16 + (lq & 1) * 8 + lr;
                int kb  = ks * 32 + (lq >> 1) * 16;
                uint32_t o = row * ROWB + kb;
                ldsm_x4(ahi[mb][0], ahi[mb][1], ahi[mb][2], ahi[mb][3], sb + S2_A_HI + o);
                ldsm_x4(alo[mb][0], alo[mb][1], alo[mb][2], alo[mb][3], sb + S2_A_LO + o);
            }
            uint32_t bhi[4][2], blo[4][2];
            #pragma unroll
            for (int g = 0; g < 2; g++) {
                int row = warp_n * 32 + g * 16 + (lq >> 1) * 8 + lr;
                int kb  = ks * 32 + (lq & 1) * 16;
                uint32_t o = row * ROWB + kb;
                ldsm_x4(bhi[2*g][0], bhi[2*g][1], bhi[2*g+1][0], bhi[2*g+1][1],
                        sb + S2_B_HI + o);
                ldsm_x4(blo[2*g][0], blo[2*g][1], blo[2*g+1][0], blo[2*g+1][1],
                        sb + S2_B_LO + o);
            }
            #pragma unroll
            for (int mb = 0; mb < 2; mb++)
                #pragma unroll
                for (int nb = 0; nb < 4; nb++) {
                    mma_bf16(acc[mb][nb], ahi[mb], bhi[nb]);
                    mma_bf16(acc[mb][nb], ahi[mb], blo[nb]);
                    mma_bf16(acc[mb][nb], alo[mb], bhi[nb]);
                }
        }
    };

    load_stage(0, 0);
    CP_COMMIT();
    for (int kc = 0; kc < 8; kc++) {
        if (kc < 7) {
            load_stage((kc + 1) & 1, kc + 1);
            CP_COMMIT();
            CP_WAIT_1();
        } else {
            CP_WAIT_0();
        }
        __syncthreads();
        compute_stage(kc & 1);
        __syncthreads();
    }

    const int gid = lane >> 2, tg = lane & 3;
    #pragma unroll
    for (int mb = 0; mb < 2; mb++) {
        int r0 = rowBase + warp_m * 32 + mb * 16 + gid;
        int r1 = r0 + 8;
        #pragma unroll
        for (int nb = 0; nb < 4; nb++) {
            int col = warp_n * 32 + nb * 8 + tg * 2;
            if (r0 < NN)
                *(float2*)&out[(size_t)r0 * OUT_F + col] =
                    make_float2(acc[mb][nb][0], acc[mb][nb][1]);
            if (r1 < NN)
                *(float2*)&out[(size_t)r1 * OUT_F + col] =
                    make_float2(acc[mb][nb][2], acc[mb][nb][3]);
        }
    }
}

// ---------------- SpMM1 (+ ReLU + dropout + bf16 split) : warp per row ------
__global__ void __launch_bounds__(256)
spmm1_kernel(const void* __restrict__ a_col,
             const float* __restrict__ a_val,
             const int* __restrict__ drop_mask) {
    int warp = (blockIdx.x * blockDim.x + threadIdx.x) >> 5;
    int lane = threadIdx.x & 31;
    if (warp >= NN) return;
    const int is64 = g_is64;
    int e0 = g_rowptr[warp];
    int e1 = g_rowptr[warp + 1];

    float4 acc0 = make_float4(0.f, 0.f, 0.f, 0.f);
    float4 acc1 = make_float4(0.f, 0.f, 0.f, 0.f);

    int e = e0;
    for (; e + 1 < e1; e += 2) {
        int   cA = load_idx(a_col, e, is64);
        int   cB = load_idx(a_col, e + 1, is64);
        float vA = __ldg(&a_val[e]);
        float vB = __ldg(&a_val[e + 1]);
        const float4* sA = (const float4*)(g_xw1 + (size_t)cA * HID) + lane * 2;
        const float4* sB = (const float4*)(g_xw1 + (size_t)cB * HID) + lane * 2;
        float4 xA0 = __ldg(sA), xA1 = __ldg(sA + 1);
        float4 xB0 = __ldg(sB), xB1 = __ldg(sB + 1);
        acc0.x = fmaf(vA, xA0.x, acc0.x); acc0.y = fmaf(vA, xA0.y, acc0.y);
        acc0.z = fmaf(vA, xA0.z, acc0.z); acc0.w = fmaf(vA, xA0.w, acc0.w);
        acc1.x = fmaf(vA, xA1.x, acc1.x); acc1.y = fmaf(vA, xA1.y, acc1.y);
        acc1.z = fmaf(vA, xA1.z, acc1.z); acc1.w = fmaf(vA, xA1.w, acc1.w);
        acc0.x = fmaf(vB, xB0.x, acc0.x); acc0.y = fmaf(vB, xB0.y, acc0.y);
        acc0.z = fmaf(vB, xB0.z, acc0.z); acc0.w = fmaf(vB, xB0.w, acc0.w);
        acc1.x = fmaf(vB, xB1.x, acc1.x); acc1.y = fmaf(vB, xB1.y, acc1.y);
        acc1.z = fmaf(vB, xB1.z, acc1.z); acc1.w = fmaf(vB, xB1.w, acc1.w);
    }
    if (e < e1) {
        int   col = load_idx(a_col, e, is64);
        float v   = __ldg(&a_val[e]);
        const float4* src = (const float4*)(g_xw1 + (size_t)col * HID) + lane * 2;
        float4 x0 = __ldg(src), x1 = __ldg(src + 1);
        acc0.x = fmaf(v, x0.x, acc0.x); acc0.y = fmaf(v, x0.y, acc0.y);
        acc0.z = fmaf(v, x0.z, acc0.z); acc0.w = fmaf(v, x0.w, acc0.w);
        acc1.x = fmaf(v, x1.x, acc1.x); acc1.y = fmaf(v, x1.y, acc1.y);
        acc1.z = fmaf(v, x1.z, acc1.z); acc1.w = fmaf(v, x1.w, acc1.w);
    }

    const int4* mrow = (const int4*)(drop_mask + (size_t)warp * HID) + lane * 2;
    int4 m0 = __ldg(mrow);
    int4 m1 = __ldg(mrow + 1);

    float r[8];
    r[0] = fmaxf(acc0.x, 0.f) * (float)m0.x * 2.0f;
    r[1] = fmaxf(acc0.y, 0.f) * (float)m0.y * 2.0f;
    r[2] = fmaxf(acc0.z, 0.f) * (float)m0.z * 2.0f;
    r[3] = fmaxf(acc0.w, 0.f) * (float)m0.w * 2.0f;
    r[4] = fmaxf(acc1.x, 0.f) * (float)m1.x * 2.0f;
    r[5] = fmaxf(acc1.y, 0.f) * (float)m1.y * 2.0f;
    r[6] = fmaxf(acc1.z, 0.f) * (float)m1.z * 2.0f;
    r[7] = fmaxf(acc1.w, 0.f) * (float)m1.w * 2.0f;

    // split to bf16 hi/lo (8 bf16 = one uint4 each)
    uint4 hi, lo;
    float h0, h1;
    h0 = bf_round(r[0]); h1 = bf_round(r[1]);
    hi.x = bf2_pack(r[0], r[1]); lo.x = bf2_pack(r[0] - h0, r[1] - h1);
    h0 = bf_round(r[2]); h1 = bf_round(r[3]);
    hi.y = bf2_pack(r[2], r[3]); lo.y = bf2_pack(r[2] - h0, r[3] - h1);
    h0 = bf_round(r[4]); h1 = bf_round(r[5]);
    hi.z = bf2_pack(r[4], r[5]); lo.z = bf2_pack(r[4] - h0, r[5] - h1);
    h0 = bf_round(r[6]); h1 = bf_round(r[7]);
    hi.w = bf2_pack(r[6], r[7]); lo.w = bf2_pack(r[6] - h0, r[7] - h1);

    *(uint4*)(g_h_hi + (size_t)warp * HID + lane * 8) = hi;
    *(uint4*)(g_h_lo + (size_t)warp * HID + lane * 8) = lo;
}

// ---------------- SpMM2 + log_softmax : warp per row ------------------------
__global__ void __launch_bounds__(256)
spmm2_lsm_kernel(const void* __restrict__ a_col,
                 const float* __restrict__ a_val,
                 float* __restrict__ out) {
    int warp = (blockIdx.x * blockDim.x + threadIdx.x) >> 5;
    int lane = threadIdx.x & 31;
    if (warp >= NN) return;
    const int is64 = g_is64;
    int e0 = g_rowptr[warp];
    int e1 = g_rowptr[warp + 1];

    float a0 = 0.f, a1 = 0.f;
    int e = e0;
    for (; e + 1 < e1; e += 2) {
        int   cA = load_idx(a_col, e, is64);
        int   cB = load_idx(a_col, e + 1, is64);
        float vA = __ldg(&a_val[e]);
        float vB = __ldg(&a_val[e + 1]);
        const float* sA = g_hw2 + (size_t)cA * OUT_F;
        const float* sB = g_hw2 + (size_t)cB * OUT_F;
        float xA0 = __ldg(&sA[lane]), xA1 = __ldg(&sA[32 + lane]);
        float xB0 = __ldg(&sB[lane]), xB1 = __ldg(&sB[32 + lane]);
        a0 = fmaf(vA, xA0, a0); a1 = fmaf(vA, xA1, a1);
        a0 = fmaf(vB, xB0, a0); a1 = fmaf(vB, xB1, a1);
    }
    if (e < e1) {
        int   col = load_idx(a_col, e, is64);
        float v   = __ldg(&a_val[e]);
        const float* src = g_hw2 + (size_t)col * OUT_F;
        a0 = fmaf(v, __ldg(&src[lane]),      a0);
        a1 = fmaf(v, __ldg(&src[32 + lane]), a1);
    }

    float m = fmaxf(a0, a1);
    #pragma unroll
    for (int off = 16; off > 0; off >>= 1)
        m = fmaxf(m, __shfl_xor_sync(0xFFFFFFFFu, m, off));
    float s = expf(a0 - m) + expf(a1 - m);
    #pragma unroll
    for (int off = 16; off > 0; off >>= 1)
        s += __shfl_xor_sync(0xFFFFFFFFu, s, off);
    float ls = logf(s) + m;

    out[(size_t)warp * OUT_F + lane]      = a0 - ls;
    out[(size_t)warp * OUT_F + 32 + lane] = a1 - ls;
}

// ---------------- launch ----------------------------------------------------
extern "C" void kernel_launch(void* const* d_in, const int* in_sizes, int n_in,
                              void* d_out, int out_size) {
    const float* X     = (const float*)d_in[0];
    const float* W1    = (const float*)d_in[1];
    const float* W2    = (const float*)d_in[2];
    const void*  a_row = d_in[3];
    const void*  a_col = d_in[4];
    const float* a_val = (const float*)d_in[5];
    const int*   dmask = (const int*)d_in[6];
    float*       out   = (float*)d_out;

    const int E = in_sizes[5];

    float *p_xw1, *p_hw2;
    cudaGetSymbolAddress((void**)&p_xw1, g_xw1);
    cudaGetSymbolAddress((void**)&p_hw2, g_hw2);

    static int smem_set = 0;
    if (!smem_set) {
        cudaFuncSetAttribute(gemm1_mma_kernel,
                             cudaFuncAttributeMaxDynamicSharedMemorySize, GSMEM_TOTAL);
        cudaFuncSetAttribute(gemm2_mma_kernel,
                             cudaFuncAttributeMaxDynamicSharedMemorySize, G2SMEM_TOTAL);
        smem_set = 1;
    }

    // 0) detect index dtype
    detect_idx_kernel<<<1, 32>>>(a_col, E);

    // 1) independent preps
    build_rowptr_kernel<<<(NN + 1 + 255) / 256, 256>>>(a_row, E);
    prep_x_kernel<<<((NN * IN_F / 4) + 255) / 256, 256>>>(X);
    prep_w1t_kernel<<<(IN_F * HID + 255) / 256, 256>>>(W1);
    prep_w2t_kernel<<<(HID * OUT_F + 255) / 256, 256>>>(W2);

    // 2) GEMM1: xw1 = X @ W1 (tensor cores)
    {
        dim3 grid((NN + 127) / 128, HID / 128);
        gemm1_mma_kernel<<<grid, 256, GSMEM_TOTAL>>>(p_xw1);
    }

    // 3) SpMM1 + relu + dropout -> h (bf16 hi/lo)
    spmm1_kernel<<<(NN * 32 + 255) / 256, 256>>>(a_col, a_val, dmask);

    // 4) GEMM2: hw2 = h @ W2 (tensor cores)
    gemm2_mma_kernel<<<(NN + 127) / 128, 256, G2SMEM_TOTAL>>>(p_hw2);

    // 5) SpMM2 + log_softmax -> out
    spmm2_lsm_kernel<<<(NN * 32 + 255) / 256, 256>>>(a_col, a_val, out);
}

// round 6
// speedup vs baseline: 1.8561x; 1.0535x over previous
#include <cuda_runtime.h>
#include <cuda_bf16.h>
#include <math.h>
#include <stdint.h>

// Problem constants
#define NN    50000
#define EE    800000
#define IN_F  512
#define HID   256
#define OUT_F 64

// ---------------- scratch (static device globals; no allocs) ----------------
__device__ float g_xw1[(size_t)NN * HID];   // X @ W1
__device__ float g_hw2[(size_t)NN * OUT_F]; // h @ W2
__device__ int   g_rowptr[NN + 1];
__device__ int   g_is64;
__device__ __nv_bfloat16 g_w1t_hi[(size_t)HID * IN_F]; // W1^T hi  [256,512]
__device__ __nv_bfloat16 g_w1t_lo[(size_t)HID * IN_F]; // W1^T lo
__device__ __nv_bfloat16 g_h_hi[(size_t)NN * HID];     // h split hi [50000,256]
__device__ __nv_bfloat16 g_h_lo[(size_t)NN * HID];     // h split lo
__device__ __nv_bfloat16 g_w2t_hi[(size_t)OUT_F * HID]; // W2^T hi [64,256]
__device__ __nv_bfloat16 g_w2t_lo[(size_t)OUT_F * HID]; // W2^T lo

// ======================= PTX helpers ========================================
__device__ __forceinline__ uint32_t smem_u32(const void* p) {
    uint32_t a;
    asm("{ .reg .u64 t; cvta.to.shared.u64 t, %1; cvt.u32.u64 %0, t; }"
        : "=r"(a) : "l"(p));
    return a;
}
__device__ __forceinline__ void cpa16(uint32_t dst, const void* src) {
    asm volatile("cp.async.cg.shared.global [%0], [%1], 16;"
                 :: "r"(dst), "l"(src) : "memory");
}
#define CP_COMMIT()  asm volatile("cp.async.commit_group;" ::: "memory")
#define CP_WAIT_1()  asm volatile("cp.async.wait_group 1;" ::: "memory")
#define CP_WAIT_0()  asm volatile("cp.async.wait_group 0;" ::: "memory")

__device__ __forceinline__ void ldsm_x4(uint32_t& r0, uint32_t& r1,
                                        uint32_t& r2, uint32_t& r3, uint32_t addr) {
    asm volatile("ldmatrix.sync.aligned.m8n8.x4.shared.b16 {%0,%1,%2,%3}, [%4];"
                 : "=r"(r0), "=r"(r1), "=r"(r2), "=r"(r3) : "r"(addr));
}
__device__ __forceinline__ void mma_bf16_2(float* c, const uint32_t* a,
                                           uint32_t b0, uint32_t b1) {
    asm volatile(
        "mma.sync.aligned.m16n8k16.row.col.f32.bf16.bf16.f32 "
        "{%0,%1,%2,%3}, {%4,%5,%6,%7}, {%8,%9}, {%0,%1,%2,%3};"
        : "+f"(c[0]), "+f"(c[1]), "+f"(c[2]), "+f"(c[3])
        : "r"(a[0]), "r"(a[1]), "r"(a[2]), "r"(a[3]), "r"(b0), "r"(b1));
}

__device__ __forceinline__ uint32_t bf2_pack(float a, float b) {
    __nv_bfloat162 t = __floats2bfloat162_rn(a, b);
    return *reinterpret_cast<uint32_t*>(&t);
}
__device__ __forceinline__ float bf_round(float x) {
    return __bfloat162float(__float2bfloat16_rn(x));
}

// ---------------- index dtype detection (int64 vs int32) --------------------
__global__ void detect_idx_kernel(const void* __restrict__ a_col_raw, int E) {
    if (threadIdx.x != 0 || blockIdx.x != 0) return;
    const long long* p = (const long long*)a_col_raw;
    int ok = 1;
    for (int i = 0; i < 16; i++) {
        long long v = p[i];
        if (v < 0 || v >= NN) { ok = 0; break; }
    }
    if (ok) {
        for (int i = 0; i < 16; i++) {
            long long v = p[E / 2 + i];
            if (v < 0 || v >= NN) { ok = 0; break; }
        }
    }
    g_is64 = ok;
}
__device__ __forceinline__ int load_idx(const void* p, int i, int is64) {
    if (is64) return (int)((const long long*)p)[i];
    return ((const int*)p)[i];
}

// ---------------- rowptr ----------------------------------------------------
__global__ void build_rowptr_kernel(const void* __restrict__ a_row, int E) {
    int r = blockIdx.x * blockDim.x + threadIdx.x;
    if (r > NN) return;
    if (r == NN) { g_rowptr[NN] = E; return; }
    const int is64 = g_is64;
    int lo = 0, hi = E;
    while (lo < hi) {
        int mid = (lo + hi) >> 1;
        if (load_idx(a_row, mid, is64) < r) lo = mid + 1; else hi = mid;
    }
    g_rowptr[r] = lo;
}

// ---------------- weight preps ----------------------------------------------
__global__ void prep_w1t_kernel(const float* __restrict__ W1) {
    int idx = blockIdx.x * blockDim.x + threadIdx.x;
    if (idx >= IN_F * HID) return;
    int n = idx >> 9, k = idx & 511;
    float v = W1[(size_t)k * HID + n];
    __nv_bfloat16 h = __float2bfloat16_rn(v);
    g_w1t_hi[idx] = h;
    g_w1t_lo[idx] = __float2bfloat16_rn(v - __bfloat162float(h));
}

__global__ void prep_w2t_kernel(const float* __restrict__ W2) {
    int idx = blockIdx.x * blockDim.x + threadIdx.x;
    if (idx >= HID * OUT_F) return;
    int n = idx >> 8, k = idx & 255;
    float v = W2[(size_t)k * OUT_F + n];
    __nv_bfloat16 h = __float2bfloat16_rn(v);
    g_w2t_hi[idx] = h;
    g_w2t_lo[idx] = __float2bfloat16_rn(v - __bfloat162float(h));
}

// ---------------- GEMM1: X@W1, CTA 128x256, fused fp32->bf16 split ----------
// 512 threads (16 warps): warp_m = wid&3 (32 rows), warp_n = wid>>2 (64 cols).
#define ROWB   80
#define XFP    160          // fp32 staging pitch (128B data + 32B pad)
#define G1_XF0 0            // 20480
#define G1_XF1 20480
#define G1_AHI 40960        // 10240 (single-buffered)
#define G1_ALO 51200
#define G1_BHI0 61440       // 20480 each
#define G1_BLO0 81920
#define G1_BHI1 102400
#define G1_BLO1 122880
#define G1_TOTAL 143360

__global__ void __launch_bounds__(512)
gemm1_mma_kernel(const float* __restrict__ X, float* __restrict__ out) {
    extern __shared__ char smem[];
    const uint32_t sm0 = smem_u32(smem);
    const int tid = threadIdx.x;
    const int wid = tid >> 5, lane = tid & 31;
    const int warp_m = wid & 3, warp_n = wid >> 2;
    const int rowBase = blockIdx.x * 128;

    float acc[2][8][4];
    #pragma unroll
    for (int i = 0; i < 2; i++)
        #pragma unroll
        for (int j = 0; j < 8; j++)
            #pragma unroll
            for (int t = 0; t < 4; t++) acc[i][j][t] = 0.f;

    auto load_stage = [&](int s, int kc) {
        int k0 = kc * 32;
        uint32_t xf = sm0 + (s ? G1_XF1 : G1_XF0);
        uint32_t bh = sm0 + (s ? G1_BHI1 : G1_BHI0);
        uint32_t bl = sm0 + (s ? G1_BLO1 : G1_BLO0);
        #pragma unroll
        for (int i = 0; i < 2; i++) {
            int c = tid + 512 * i;          // 0..1023
            int row = c >> 3, q = c & 7;    // X: 8x16B per row
            int rg = rowBase + row; if (rg >= NN) rg = NN - 1;
            cpa16(xf + row * XFP + q * 16, X + (size_t)rg * IN_F + k0 + q * 4);
        }
        #pragma unroll
        for (int i = 0; i < 2; i++) {
            int c = tid + 512 * i;          // 0..1023
            int row = c >> 2, q = c & 3;    // B: 4x16B per row, 256 rows
            uint32_t o = row * ROWB + q * 16;
            cpa16(bh + o, g_w1t_hi + (size_t)row * IN_F + k0 + q * 8);
            cpa16(bl + o, g_w1t_lo + (size_t)row * IN_F + k0 + q * 8);
        }
    };

    auto convert_stage = [&](int s) {
        const char* xf = smem + (s ? G1_XF1 : G1_XF0);
        int row = tid >> 2, q = tid & 3;    // 8 floats per thread
        const float4 v0 = *(const float4*)(xf + row * XFP + q * 32);
        const float4 v1 = *(const float4*)(xf + row * XFP + q * 32 + 16);
        uint4 hi, lo;
        float h0, h1;
        h0 = bf_round(v0.x); h1 = bf_round(v0.y);
        hi.x = bf2_pack(v0.x, v0.y); lo.x = bf2_pack(v0.x - h0, v0.y - h1);
        h0 = bf_round(v0.z); h1 = bf_round(v0.w);
        hi.y = bf2_pack(v0.z, v0.w); lo.y = bf2_pack(v0.z - h0, v0.w - h1);
        h0 = bf_round(v1.x); h1 = bf_round(v1.y);
        hi.z = bf2_pack(v1.x, v1.y); lo.z = bf2_pack(v1.x - h0, v1.y - h1);
        h0 = bf_round(v1.z); h1 = bf_round(v1.w);
        hi.w = bf2_pack(v1.z, v1.w); lo.w = bf2_pack(v1.z - h0, v1.w - h1);
        *(uint4*)(smem + G1_AHI + row * ROWB + q * 16) = hi;
        *(uint4*)(smem + G1_ALO + row * ROWB + q * 16) = lo;
    };

    const int lq = lane >> 3, lr = lane & 7;

    auto compute_stage = [&](int s) {
        uint32_t bh_base = sm0 + (s ? G1_BHI1 : G1_BHI0);
        uint32_t bl_base = sm0 + (s ? G1_BLO1 : G1_BLO0);
        #pragma unroll
        for (int ks = 0; ks < 2; ks++) {
            uint32_t ahi[2][4], alo[2][4];
            #pragma unroll
            for (int mb = 0; mb < 2; mb++) {
                int row = warp_m * 32 + mb * 16 + (lq & 1) * 8 + lr;
                int kb  = ks * 32 + (lq >> 1) * 16;
                uint32_t o = row * ROWB + kb;
                ldsm_x4(ahi[mb][0], ahi[mb][1], ahi[mb][2], ahi[mb][3], sm0 + G1_AHI + o);
                ldsm_x4(alo[mb][0], alo[mb][1], alo[mb][2], alo[mb][3], sm0 + G1_ALO + o);
            }
            #pragma unroll
            for (int g = 0; g < 4; g++) {
                int row = warp_n * 64 + g * 16 + (lq >> 1) * 8 + lr;
                int kb  = ks * 32 + (lq & 1) * 16;
                uint32_t o = row * ROWB + kb;
                uint32_t bh0, bh1, bh2, bh3, bl0, bl1, bl2, bl3;
                ldsm_x4(bh0, bh1, bh2, bh3, bh_base + o);
                ldsm_x4(bl0, bl1, bl2, bl3, bl_base + o);
                #pragma unroll
                for (int mb = 0; mb < 2; mb++) {
                    mma_bf16_2(acc[mb][2*g],   ahi[mb], bh0, bh1);
                    mma_bf16_2(acc[mb][2*g],   ahi[mb], bl0, bl1);
                    mma_bf16_2(acc[mb][2*g],   alo[mb], bh0, bh1);
                    mma_bf16_2(acc[mb][2*g+1], ahi[mb], bh2, bh3);
                    mma_bf16_2(acc[mb][2*g+1], ahi[mb], bl2, bl3);
                    mma_bf16_2(acc[mb][2*g+1], alo[mb], bh2, bh3);
                }
            }
        }
    };

    load_stage(0, 0);
    CP_COMMIT();
    for (int kc = 0; kc < 16; kc++) {
        if (kc < 15) {
            load_stage((kc + 1) & 1, kc + 1);
            CP_COMMIT();
            CP_WAIT_1();
        } else {
            CP_WAIT_0();
        }
        __syncthreads();
        convert_stage(kc & 1);
        __syncthreads();
        compute_stage(kc & 1);
        __syncthreads();
    }

    const int gid = lane >> 2, tg = lane & 3;
    #pragma unroll
    for (int mb = 0; mb < 2; mb++) {
        int r0 = rowBase + warp_m * 32 + mb * 16 + gid;
        int r1 = r0 + 8;
        #pragma unroll
        for (int nb = 0; nb < 8; nb++) {
            int col = warp_n * 64 + nb * 8 + tg * 2;
            if (r0 < NN)
                *(float2*)&out[(size_t)r0 * HID + col] =
                    make_float2(acc[mb][nb][0], acc[mb][nb][1]);
            if (r1 < NN)
                *(float2*)&out[(size_t)r1 * HID + col] =
                    make_float2(acc[mb][nb][2], acc[mb][nb][3]);
        }
    }
}

// ---------------- GEMM2 via mma.sync bf16 (3-term split) --------------------
#define S2_A_HI 0
#define S2_A_LO 10240
#define S2_B_HI 20480
#define S2_B_LO 25600
#define STG2    30720
#define G2SMEM_TOTAL (2 * STG2)   // 61440

__global__ void __launch_bounds__(256)
gemm2_mma_kernel(float* __restrict__ out) {
    extern __shared__ char smem[];
    const uint32_t sm0 = smem_u32(smem);
    const int tid = threadIdx.x;
    const int wid = tid >> 5, lane = tid & 31;
    const int warp_m = wid & 3, warp_n = wid >> 2;
    const int rowBase = blockIdx.x * 128;

    float acc[2][4][4];
    #pragma unroll
    for (int i = 0; i < 2; i++)
        #pragma unroll
        for (int j = 0; j < 4; j++)
            #pragma unroll
            for (int t = 0; t < 4; t++) acc[i][j][t] = 0.f;

    auto load_stage = [&](int s, int kc) {
        int k0 = kc * 32;
        uint32_t sb = sm0 + s * STG2;
        #pragma unroll
        for (int i = 0; i < 2; i++) {
            int c = tid + 256 * i;
            int row = c >> 2, q = c & 3;
            int rg = rowBase + row; if (rg >= NN) rg = NN - 1;
            uint32_t o = row * ROWB + q * 16;
            cpa16(sb + S2_A_HI + o, g_h_hi + (size_t)rg * HID + k0 + q * 8);
            cpa16(sb + S2_A_LO + o, g_h_lo + (size_t)rg * HID + k0 + q * 8);
        }
        {
            int row = tid >> 2, q = tid & 3;
            uint32_t o = row * ROWB + q * 16;
            cpa16(sb + S2_B_HI + o, g_w2t_hi + (size_t)row * HID + k0 + q * 8);
            cpa16(sb + S2_B_LO + o, g_w2t_lo + (size_t)row * HID + k0 + q * 8);
        }
    };

    const int lq = lane >> 3, lr = lane & 7;

    auto compute_stage = [&](int s) {
        uint32_t sb = sm0 + s * STG2;
        #pragma unroll
        for (int ks = 0; ks < 2; ks++) {
            uint32_t ahi[2][4], alo[2][4];
            #pragma unroll
            for (int mb = 0; mb < 2; mb++) {
                int row = warp_m * 32 + mb * 16 + (lq & 1) * 8 + lr;
                int kb  = ks * 32 + (lq >> 1) * 16;
                uint32_t o = row * ROWB + kb;
                ldsm_x4(ahi[mb][0], ahi[mb][1], ahi[mb][2], ahi[mb][3], sb + S2_A_HI + o);
                ldsm_x4(alo[mb][0], alo[mb][1], alo[mb][2], alo[mb][3], sb + S2_A_LO + o);
            }
            #pragma unroll
            for (int g = 0; g < 2; g++) {
                int row = warp_n * 32 + g * 16 + (lq >> 1) * 8 + lr;
                int kb  = ks * 32 + (lq & 1) * 16;
                uint32_t o = row * ROWB + kb;
                uint32_t bh0, bh1, bh2, bh3, bl0, bl1, bl2, bl3;
                ldsm_x4(bh0, bh1, bh2, bh3, sb + S2_B_HI + o);
                ldsm_x4(bl0, bl1, bl2, bl3, sb + S2_B_LO + o);
                #pragma unroll
                for (int mb = 0; mb < 2; mb++) {
                    mma_bf16_2(acc[mb][2*g],   ahi[mb], bh0, bh1);
                    mma_bf16_2(acc[mb][2*g],   ahi[mb], bl0, bl1);
                    mma_bf16_2(acc[mb][2*g],   alo[mb], bh0, bh1);
                    mma_bf16_2(acc[mb][2*g+1], ahi[mb], bh2, bh3);
                    mma_bf16_2(acc[mb][2*g+1], ahi[mb], bl2, bl3);
                    mma_bf16_2(acc[mb][2*g+1], alo[mb], bh2, bh3);
                }
            }
        }
    };

    load_stage(0, 0);
    CP_COMMIT();
    for (int kc = 0; kc < 8; kc++) {
        if (kc < 7) {
            load_stage((kc + 1) & 1, kc + 1);
            CP_COMMIT();
            CP_WAIT_1();
        } else {
            CP_WAIT_0();
        }
        __syncthreads();
        compute_stage(kc & 1);
        __syncthreads();
    }

    const int gid = lane >> 2, tg = lane & 3;
    #pragma unroll
    for (int mb = 0; mb < 2; mb++) {
        int r0 = rowBase + warp_m * 32 + mb * 16 + gid;
        int r1 = r0 + 8;
        #pragma unroll
        for (int nb = 0; nb < 4; nb++) {
            int col = warp_n * 32 + nb * 8 + tg * 2;
            if (r0 < NN)
                *(float2*)&out[(size_t)r0 * OUT_F + col] =
                    make_float2(acc[mb][nb][0], acc[mb][nb][1]);
            if (r1 < NN)
                *(float2*)&out[(size_t)r1 * OUT_F + col] =
                    make_float2(acc[mb][nb][2], acc[mb][nb][3]);
        }
    }
}

// ---------------- SpMM1 (+ ReLU + dropout + bf16 split) : warp per row ------
__global__ void __launch_bounds__(256)
spmm1_kernel(const void* __restrict__ a_col,
             const float* __restrict__ a_val,
             const int* __restrict__ drop_mask) {
    int warp = (blockIdx.x * blockDim.x + threadIdx.x) >> 5;
    int lane = threadIdx.x & 31;
    if (warp >= NN) return;
    const int is64 = g_is64;
    int e0 = g_rowptr[warp];
    int e1 = g_rowptr[warp + 1];

    float4 acc0 = make_float4(0.f, 0.f, 0.f, 0.f);
    float4 acc1 = make_float4(0.f, 0.f, 0.f, 0.f);

    int e = e0;
    for (; e + 3 < e1; e += 4) {
        int cc[4]; float vv[4];
        #pragma unroll
        for (int j = 0; j < 4; j++) {
            cc[j] = load_idx(a_col, e + j, is64);
            vv[j] = __ldg(&a_val[e + j]);
        }
        float4 x0[4], x1[4];
        #pragma unroll
        for (int j = 0; j < 4; j++) {
            const float4* s = (const float4*)(g_xw1 + (size_t)cc[j] * HID) + lane * 2;
            x0[j] = __ldg(s);
            x1[j] = __ldg(s + 1);
        }
        #pragma unroll
        for (int j = 0; j < 4; j++) {
            acc0.x = fmaf(vv[j], x0[j].x, acc0.x); acc0.y = fmaf(vv[j], x0[j].y, acc0.y);
            acc0.z = fmaf(vv[j], x0[j].z, acc0.z); acc0.w = fmaf(vv[j], x0[j].w, acc0.w);
            acc1.x = fmaf(vv[j], x1[j].x, acc1.x); acc1.y = fmaf(vv[j], x1[j].y, acc1.y);
            acc1.z = fmaf(vv[j], x1[j].z, acc1.z); acc1.w = fmaf(vv[j], x1[j].w, acc1.w);
        }
    }
    for (; e < e1; e++) {
        int   col = load_idx(a_col, e, is64);
        float v   = __ldg(&a_val[e]);
        const float4* src = (const float4*)(g_xw1 + (size_t)col * HID) + lane * 2;
        float4 x0 = __ldg(src), x1 = __ldg(src + 1);
        acc0.x = fmaf(v, x0.x, acc0.x); acc0.y = fmaf(v, x0.y, acc0.y);
        acc0.z = fmaf(v, x0.z, acc0.z); acc0.w = fmaf(v, x0.w, acc0.w);
        acc1.x = fmaf(v, x1.x, acc1.x); acc1.y = fmaf(v, x1.y, acc1.y);
        acc1.z = fmaf(v, x1.z, acc1.z); acc1.w = fmaf(v, x1.w, acc1.w);
    }

    const int4* mrow = (const int4*)(drop_mask + (size_t)warp * HID) + lane * 2;
    int4 m0 = __ldg(mrow);
    int4 m1 = __ldg(mrow + 1);

    float r[8];
    r[0] = fmaxf(acc0.x, 0.f) * (float)m0.x * 2.0f;
    r[1] = fmaxf(acc0.y, 0.f) * (float)m0.y * 2.0f;
    r[2] = fmaxf(acc0.z, 0.f) * (float)m0.z * 2.0f;
    r[3] = fmaxf(acc0.w, 0.f) * (float)m0.w * 2.0f;
    r[4] = fmaxf(acc1.x, 0.f) * (float)m1.x * 2.0f;
    r[5] = fmaxf(acc1.y, 0.f) * (float)m1.y * 2.0f;
    r[6] = fmaxf(acc1.z, 0.f) * (float)m1.z * 2.0f;
    r[7] = fmaxf(acc1.w, 0.f) * (float)m1.w * 2.0f;

    uint4 hi, lo;
    float h0, h1;
    h0 = bf_round(r[0]); h1 = bf_round(r[1]);
    hi.x = bf2_pack(r[0], r[1]); lo.x = bf2_pack(r[0] - h0, r[1] - h1);
    h0 = bf_round(r[2]); h1 = bf_round(r[3]);
    hi.y = bf2_pack(r[2], r[3]); lo.y = bf2_pack(r[2] - h0, r[3] - h1);
    h0 = bf_round(r[4]); h1 = bf_round(r[5]);
    hi.z = bf2_pack(r[4], r[5]); lo.z = bf2_pack(r[4] - h0, r[5] - h1);
    h0 = bf_round(r[6]); h1 = bf_round(r[7]);
    hi.w = bf2_pack(r[6], r[7]); lo.w = bf2_pack(r[6] - h0, r[7] - h1);

    *(uint4*)(g_h_hi + (size_t)warp * HID + lane * 8) = hi;
    *(uint4*)(g_h_lo + (size_t)warp * HID + lane * 8) = lo;
}

// ---------------- SpMM2 + log_softmax : warp per row ------------------------
__global__ void __launch_bounds__(256)
spmm2_lsm_kernel(const void* __restrict__ a_col,
                 const float* __restrict__ a_val,
                 float* __restrict__ out) {
    int warp = (blockIdx.x * blockDim.x + threadIdx.x) >> 5;
    int lane = threadIdx.x & 31;
    if (warp >= NN) return;
    const int is64 = g_is64;
    int e0 = g_rowptr[warp];
    int e1 = g_rowptr[warp + 1];

    float a0 = 0.f, a1 = 0.f;
    int e = e0;
    for (; e + 3 < e1; e += 4) {
        int cc[4]; float vv[4];
        #pragma unroll
        for (int j = 0; j < 4; j++) {
            cc[j] = load_idx(a_col, e + j, is64);
            vv[j] = __ldg(&a_val[e + j]);
        }
        float x0[4], x1[4];
        #pragma unroll
        for (int j = 0; j < 4; j++) {
            const float* s = g_hw2 + (size_t)cc[j] * OUT_F;
            x0[j] = __ldg(&s[lane]);
            x1[j] = __ldg(&s[32 + lane]);
        }
        #pragma unroll
        for (int j = 0; j < 4; j++) {
            a0 = fmaf(vv[j], x0[j], a0);
            a1 = fmaf(vv[j], x1[j], a1);
        }
    }
    for (; e < e1; e++) {
        int   col = load_idx(a_col, e, is64);
        float v   = __ldg(&a_val[e]);
        const float* src = g_hw2 + (size_t)col * OUT_F;
        a0 = fmaf(v, __ldg(&src[lane]),      a0);
        a1 = fmaf(v, __ldg(&src[32 + lane]), a1);
    }

    float m = fmaxf(a0, a1);
    #pragma unroll
    for (int off = 16; off > 0; off >>= 1)
        m = fmaxf(m, __shfl_xor_sync(0xFFFFFFFFu, m, off));
    float s = expf(a0 - m) + expf(a1 - m);
    #pragma unroll
    for (int off = 16; off > 0; off >>= 1)
        s += __shfl_xor_sync(0xFFFFFFFFu, s, off);
    float ls = logf(s) + m;

    out[(size_t)warp * OUT_F + lane]      = a0 - ls;
    out[(size_t)warp * OUT_F + 32 + lane] = a1 - ls;
}

// ---------------- launch ----------------------------------------------------
extern "C" void kernel_launch(void* const* d_in, const int* in_sizes, int n_in,
                              void* d_out, int out_size) {
    const float* X     = (const float*)d_in[0];
    const float* W1    = (const float*)d_in[1];
    const float* W2    = (const float*)d_in[2];
    const void*  a_row = d_in[3];
    const void*  a_col = d_in[4];
    const float* a_val = (const float*)d_in[5];
    const int*   dmask = (const int*)d_in[6];
    float*       out   = (float*)d_out;

    const int E = in_sizes[5];

    float *p_xw1, *p_hw2;
    cudaGetSymbolAddress((void**)&p_xw1, g_xw1);
    cudaGetSymbolAddress((void**)&p_hw2, g_hw2);

    static int smem_set = 0;
    if (!smem_set) {
        cudaFuncSetAttribute(gemm1_mma_kernel,
                             cudaFuncAttributeMaxDynamicSharedMemorySize, G1_TOTAL);
        cudaFuncSetAttribute(gemm2_mma_kernel,
                             cudaFuncAttributeMaxDynamicSharedMemorySize, G2SMEM_TOTAL);
        smem_set = 1;
    }

    // 0) detect index dtype
    detect_idx_kernel<<<1, 32>>>(a_col, E);

    // 1) independent preps (prep_x eliminated — fused into GEMM1)
    build_rowptr_kernel<<<(NN + 1 + 255) / 256, 256>>>(a_row, E);
    prep_w1t_kernel<<<(IN_F * HID + 255) / 256, 256>>>(W1);
    prep_w2t_kernel<<<(HID * OUT_F + 255) / 256, 256>>>(W2);

    // 2) GEMM1: xw1 = X @ W1 (tensor cores, fused split, full-N tile)
    gemm1_mma_kernel<<<(NN + 127) / 128, 512, G1_TOTAL>>>(X, p_xw1);

    // 3) SpMM1 + relu + dropout -> h (bf16 hi/lo)
    spmm1_kernel<<<(NN * 32 + 255) / 256, 256>>>(a_col, a_val, dmask);

    // 4) GEMM2: hw2 = h @ W2 (tensor cores)
    gemm2_mma_kernel<<<(NN + 127) / 128, 256, G2SMEM_TOTAL>>>(p_hw2);

    // 5) SpMM2 + log_softmax -> out
    spmm2_lsm_kernel<<<(NN * 32 + 255) / 256, 256>>>(a_col, a_val, out);
}

// round 7
// speedup vs baseline: 2.0211x; 1.0889x over previous
#include <cuda_runtime.h>
#include <cuda_bf16.h>
#include <cuda_fp16.h>
#include <math.h>
#include <stdint.h>

// Problem constants
#define NN    50000
#define EE    800000
#define IN_F  512
#define HID   256
#define OUT_F 64

// ---------------- scratch (static device globals; no allocs) ----------------
__device__ __half g_xw1h[(size_t)NN * HID];  // X @ W1 (fp16, gather table)
__device__ __half g_hw2h[(size_t)NN * OUT_F];// h @ W2 (fp16, gather table)
__device__ int   g_rowptr[NN + 1];
__device__ int   g_is64;
__device__ __nv_bfloat16 g_w1t_hi[(size_t)HID * IN_F]; // W1^T hi  [256,512]
__device__ __nv_bfloat16 g_w1t_lo[(size_t)HID * IN_F]; // W1^T lo
__device__ __nv_bfloat16 g_h_hi[(size_t)NN * HID];     // h split hi [50000,256]
__device__ __nv_bfloat16 g_h_lo[(size_t)NN * HID];     // h split lo
__device__ __nv_bfloat16 g_w2t_hi[(size_t)OUT_F * HID]; // W2^T hi [64,256]
__device__ __nv_bfloat16 g_w2t_lo[(size_t)OUT_F * HID]; // W2^T lo

// ======================= PTX helpers ========================================
__device__ __forceinline__ uint32_t smem_u32(const void* p) {
    uint32_t a;
    asm("{ .reg .u64 t; cvta.to.shared.u64 t, %1; cvt.u32.u64 %0, t; }"
        : "=r"(a) : "l"(p));
    return a;
}
__device__ __forceinline__ void cpa16(uint32_t dst, const void* src) {
    asm volatile("cp.async.cg.shared.global [%0], [%1], 16;"
                 :: "r"(dst), "l"(src) : "memory");
}
#define CP_COMMIT()  asm volatile("cp.async.commit_group;" ::: "memory")
#define CP_WAIT_1()  asm volatile("cp.async.wait_group 1;" ::: "memory")
#define CP_WAIT_0()  asm volatile("cp.async.wait_group 0;" ::: "memory")

__device__ __forceinline__ void ldsm_x4(uint32_t& r0, uint32_t& r1,
                                        uint32_t& r2, uint32_t& r3, uint32_t addr) {
    asm volatile("ldmatrix.sync.aligned.m8n8.x4.shared.b16 {%0,%1,%2,%3}, [%4];"
                 : "=r"(r0), "=r"(r1), "=r"(r2), "=r"(r3) : "r"(addr));
}
__device__ __forceinline__ void mma_bf16_2(float* c, const uint32_t* a,
                                           uint32_t b0, uint32_t b1) {
    asm volatile(
        "mma.sync.aligned.m16n8k16.row.col.f32.bf16.bf16.f32 "
        "{%0,%1,%2,%3}, {%4,%5,%6,%7}, {%8,%9}, {%0,%1,%2,%3};"
        : "+f"(c[0]), "+f"(c[1]), "+f"(c[2]), "+f"(c[3])
        : "r"(a[0]), "r"(a[1]), "r"(a[2]), "r"(a[3]), "r"(b0), "r"(b1));
}

__device__ __forceinline__ uint32_t bf2_pack(float a, float b) {
    __nv_bfloat162 t = __floats2bfloat162_rn(a, b);
    return *reinterpret_cast<uint32_t*>(&t);
}
__device__ __forceinline__ float bf_round(float x) {
    return __bfloat162float(__float2bfloat16_rn(x));
}

// ---------------- index dtype detection (int64 vs int32) --------------------
__global__ void detect_idx_kernel(const void* __restrict__ a_col_raw, int E) {
    if (threadIdx.x != 0 || blockIdx.x != 0) return;
    const long long* p = (const long long*)a_col_raw;
    int ok = 1;
    for (int i = 0; i < 16; i++) {
        long long v = p[i];
        if (v < 0 || v >= NN) { ok = 0; break; }
    }
    if (ok) {
        for (int i = 0; i < 16; i++) {
            long long v = p[E / 2 + i];
            if (v < 0 || v >= NN) { ok = 0; break; }
        }
    }
    g_is64 = ok;
}
__device__ __forceinline__ int load_idx(const void* p, int i, int is64) {
    if (is64) return (int)((const long long*)p)[i];
    return ((const int*)p)[i];
}

// ---------------- merged weight prep ----------------------------------------
__global__ void prep_w_kernel(const float* __restrict__ W1,
                              const float* __restrict__ W2) {
    int idx = blockIdx.x * blockDim.x + threadIdx.x;
    if (idx < IN_F * HID) {
        int n = idx >> 9, k = idx & 511;
        float v = W1[(size_t)k * HID + n];
        __nv_bfloat16 h = __float2bfloat16_rn(v);
        g_w1t_hi[idx] = h;
        g_w1t_lo[idx] = __float2bfloat16_rn(v - __bfloat162float(h));
    } else {
        int j = idx - IN_F * HID;
        if (j < HID * OUT_F) {
            int n = j >> 8, k = j & 255;
            float v = W2[(size_t)k * OUT_F + n];
            __nv_bfloat16 h = __float2bfloat16_rn(v);
            g_w2t_hi[j] = h;
            g_w2t_lo[j] = __float2bfloat16_rn(v - __bfloat162float(h));
        }
    }
}

// ---------------- rowptr ----------------------------------------------------
__global__ void build_rowptr_kernel(const void* __restrict__ a_row, int E) {
    int r = blockIdx.x * blockDim.x + threadIdx.x;
    if (r > NN) return;
    if (r == NN) { g_rowptr[NN] = E; return; }
    const int is64 = g_is64;
    int lo = 0, hi = E;
    while (lo < hi) {
        int mid = (lo + hi) >> 1;
        if (load_idx(a_row, mid, is64) < r) lo = mid + 1; else hi = mid;
    }
    g_rowptr[r] = lo;
}

// ---------------- GEMM1: X@W1, CTA 128x256, fused fp32->bf16 split ----------
#define ROWB   80
#define XFP    160
#define G1_XF0 0
#define G1_XF1 20480
#define G1_AHI 40960
#define G1_ALO 51200
#define G1_BHI0 61440
#define G1_BLO0 81920
#define G1_BHI1 102400
#define G1_BLO1 122880
#define G1_TOTAL 143360

__global__ void __launch_bounds__(512)
gemm1_mma_kernel(const float* __restrict__ X, __half* __restrict__ outh) {
    extern __shared__ char smem[];
    const uint32_t sm0 = smem_u32(smem);
    const int tid = threadIdx.x;
    const int wid = tid >> 5, lane = tid & 31;
    const int warp_m = wid & 3, warp_n = wid >> 2;
    const int rowBase = blockIdx.x * 128;

    float acc[2][8][4];
    #pragma unroll
    for (int i = 0; i < 2; i++)
        #pragma unroll
        for (int j = 0; j < 8; j++)
            #pragma unroll
            for (int t = 0; t < 4; t++) acc[i][j][t] = 0.f;

    auto load_stage = [&](int s, int kc) {
        int k0 = kc * 32;
        uint32_t xf = sm0 + (s ? G1_XF1 : G1_XF0);
        uint32_t bh = sm0 + (s ? G1_BHI1 : G1_BHI0);
        uint32_t bl = sm0 + (s ? G1_BLO1 : G1_BLO0);
        #pragma unroll
        for (int i = 0; i < 2; i++) {
            int c = tid + 512 * i;
            int row = c >> 3, q = c & 7;
            int rg = rowBase + row; if (rg >= NN) rg = NN - 1;
            cpa16(xf + row * XFP + q * 16, X + (size_t)rg * IN_F + k0 + q * 4);
        }
        #pragma unroll
        for (int i = 0; i < 2; i++) {
            int c = tid + 512 * i;
            int row = c >> 2, q = c & 3;
            uint32_t o = row * ROWB + q * 16;
            cpa16(bh + o, g_w1t_hi + (size_t)row * IN_F + k0 + q * 8);
            cpa16(bl + o, g_w1t_lo + (size_t)row * IN_F + k0 + q * 8);
        }
    };

    auto convert_stage = [&](int s) {
        const char* xf = smem + (s ? G1_XF1 : G1_XF0);
        int row = tid >> 2, q = tid & 3;
        const float4 v0 = *(const float4*)(xf + row * XFP + q * 32);
        const float4 v1 = *(const float4*)(xf + row * XFP + q * 32 + 16);
        uint4 hi, lo;
        float h0, h1;
        h0 = bf_round(v0.x); h1 = bf_round(v0.y);
        hi.x = bf2_pack(v0.x, v0.y); lo.x = bf2_pack(v0.x - h0, v0.y - h1);
        h0 = bf_round(v0.z); h1 = bf_round(v0.w);
        hi.y = bf2_pack(v0.z, v0.w); lo.y = bf2_pack(v0.z - h0, v0.w - h1);
        h0 = bf_round(v1.x); h1 = bf_round(v1.y);
        hi.z = bf2_pack(v1.x, v1.y); lo.z = bf2_pack(v1.x - h0, v1.y - h1);
        h0 = bf_round(v1.z); h1 = bf_round(v1.w);
        hi.w = bf2_pack(v1.z, v1.w); lo.w = bf2_pack(v1.z - h0, v1.w - h1);
        *(uint4*)(smem + G1_AHI + row * ROWB + q * 16) = hi;
        *(uint4*)(smem + G1_ALO + row * ROWB + q * 16) = lo;
    };

    const int lq = lane >> 3, lr = lane & 7;

    auto compute_stage = [&](int s) {
        uint32_t bh_base = sm0 + (s ? G1_BHI1 : G1_BHI0);
        uint32_t bl_base = sm0 + (s ? G1_BLO1 : G1_BLO0);
        #pragma unroll
        for (int ks = 0; ks < 2; ks++) {
            uint32_t ahi[2][4], alo[2][4];
            #pragma unroll
            for (int mb = 0; mb < 2; mb++) {
                int row = warp_m * 32 + mb * 16 + (lq & 1) * 8 + lr;
                int kb  = ks * 32 + (lq >> 1) * 16;
                uint32_t o = row * ROWB + kb;
                ldsm_x4(ahi[mb][0], ahi[mb][1], ahi[mb][2], ahi[mb][3], sm0 + G1_AHI + o);
                ldsm_x4(alo[mb][0], alo[mb][1], alo[mb][2], alo[mb][3], sm0 + G1_ALO + o);
            }
            #pragma unroll
            for (int g = 0; g < 4; g++) {
                int row = warp_n * 64 + g * 16 + (lq >> 1) * 8 + lr;
                int kb  = ks * 32 + (lq & 1) * 16;
                uint32_t o = row * ROWB + kb;
                uint32_t bh0, bh1, bh2, bh3, bl0, bl1, bl2, bl3;
                ldsm_x4(bh0, bh1, bh2, bh3, bh_base + o);
                ldsm_x4(bl0, bl1, bl2, bl3, bl_base + o);
                #pragma unroll
                for (int mb = 0; mb < 2; mb++) {
                    mma_bf16_2(acc[mb][2*g],   ahi[mb], bh0, bh1);
                    mma_bf16_2(acc[mb][2*g],   ahi[mb], bl0, bl1);
                    mma_bf16_2(acc[mb][2*g],   alo[mb], bh0, bh1);
                    mma_bf16_2(acc[mb][2*g+1], ahi[mb], bh2, bh3);
                    mma_bf16_2(acc[mb][2*g+1], ahi[mb], bl2, bl3);
                    mma_bf16_2(acc[mb][2*g+1], alo[mb], bh2, bh3);
                }
            }
        }
    };

    load_stage(0, 0);
    CP_COMMIT();
    for (int kc = 0; kc < 16; kc++) {
        if (kc < 15) {
            load_stage((kc + 1) & 1, kc + 1);
            CP_COMMIT();
            CP_WAIT_1();
        } else {
            CP_WAIT_0();
        }
        __syncthreads();
        convert_stage(kc & 1);
        __syncthreads();
        compute_stage(kc & 1);
        __syncthreads();
    }

    const int gid = lane >> 2, tg = lane & 3;
    #pragma unroll
    for (int mb = 0; mb < 2; mb++) {
        int r0 = rowBase + warp_m * 32 + mb * 16 + gid;
        int r1 = r0 + 8;
        #pragma unroll
        for (int nb = 0; nb < 8; nb++) {
            int col = warp_n * 64 + nb * 8 + tg * 2;
            if (r0 < NN)
                *(__half2*)&outh[(size_t)r0 * HID + col] =
                    __floats2half2_rn(acc[mb][nb][0], acc[mb][nb][1]);
            if (r1 < NN)
                *(__half2*)&outh[(size_t)r1 * HID + col] =
                    __floats2half2_rn(acc[mb][nb][2], acc[mb][nb][3]);
        }
    }
}

// ---------------- GEMM2 via mma.sync bf16 (3-term split) --------------------
#define S2_A_HI 0
#define S2_A_LO 10240
#define S2_B_HI 20480
#define S2_B_LO 25600
#define STG2    30720
#define G2SMEM_TOTAL (2 * STG2)   // 61440

__global__ void __launch_bounds__(256)
gemm2_mma_kernel(__half* __restrict__ outh) {
    extern __shared__ char smem[];
    const uint32_t sm0 = smem_u32(smem);
    const int tid = threadIdx.x;
    const int wid = tid >> 5, lane = tid & 31;
    const int warp_m = wid & 3, warp_n = wid >> 2;
    const int rowBase = blockIdx.x * 128;

    float acc[2][4][4];
    #pragma unroll
    for (int i = 0; i < 2; i++)
        #pragma unroll
        for (int j = 0; j < 4; j++)
            #pragma unroll
            for (int t = 0; t < 4; t++) acc[i][j][t] = 0.f;

    auto load_stage = [&](int s, int kc) {
        int k0 = kc * 32;
        uint32_t sb = sm0 + s * STG2;
        #pragma unroll
        for (int i = 0; i < 2; i++) {
            int c = tid + 256 * i;
            int row = c >> 2, q = c & 3;
            int rg = rowBase + row; if (rg >= NN) rg = NN - 1;
            uint32_t o = row * ROWB + q * 16;
            cpa16(sb + S2_A_HI + o, g_h_hi + (size_t)rg * HID + k0 + q * 8);
            cpa16(sb + S2_A_LO + o, g_h_lo + (size_t)rg * HID + k0 + q * 8);
        }
        {
            int row = tid >> 2, q = tid & 3;
            uint32_t o = row * ROWB + q * 16;
            cpa16(sb + S2_B_HI + o, g_w2t_hi + (size_t)row * HID + k0 + q * 8);
            cpa16(sb + S2_B_LO + o, g_w2t_lo + (size_t)row * HID + k0 + q * 8);
        }
    };

    const int lq = lane >> 3, lr = lane & 7;

    auto compute_stage = [&](int s) {
        uint32_t sb = sm0 + s * STG2;
        #pragma unroll
        for (int ks = 0; ks < 2; ks++) {
            uint32_t ahi[2][4], alo[2][4];
            #pragma unroll
            for (int mb = 0; mb < 2; mb++) {
                int row = warp_m * 32 + mb * 16 + (lq & 1) * 8 + lr;
                int kb  = ks * 32 + (lq >> 1) * 16;
                uint32_t o = row * ROWB + kb;
                ldsm_x4(ahi[mb][0], ahi[mb][1], ahi[mb][2], ahi[mb][3], sb + S2_A_HI + o);
                ldsm_x4(alo[mb][0], alo[mb][1], alo[mb][2], alo[mb][3], sb + S2_A_LO + o);
            }
            #pragma unroll
            for (int g = 0; g < 2; g++) {
                int row = warp_n * 32 + g * 16 + (lq >> 1) * 8 + lr;
                int kb  = ks * 32 + (lq & 1) * 16;
                uint32_t o = row * ROWB + kb;
                uint32_t bh0, bh1, bh2, bh3, bl0, bl1, bl2, bl3;
                ldsm_x4(bh0, bh1, bh2, bh3, sb + S2_B_HI + o);
                ldsm_x4(bl0, bl1, bl2, bl3, sb + S2_B_LO + o);
                #pragma unroll
                for (int mb = 0; mb < 2; mb++) {
                    mma_bf16_2(acc[mb][2*g],   ahi[mb], bh0, bh1);
                    mma_bf16_2(acc[mb][2*g],   ahi[mb], bl0, bl1);
                    mma_bf16_2(acc[mb][2*g],   alo[mb], bh0, bh1);
                    mma_bf16_2(acc[mb][2*g+1], ahi[mb], bh2, bh3);
                    mma_bf16_2(acc[mb][2*g+1], ahi[mb], bl2, bl3);
                    mma_bf16_2(acc[mb][2*g+1], alo[mb], bh2, bh3);
                }
            }
        }
    };

    load_stage(0, 0);
    CP_COMMIT();
    for (int kc = 0; kc < 8; kc++) {
        if (kc < 7) {
            load_stage((kc + 1) & 1, kc + 1);
            CP_COMMIT();
            CP_WAIT_1();
        } else {
            CP_WAIT_0();
        }
        __syncthreads();
        compute_stage(kc & 1);
        __syncthreads();
    }

    const int gid = lane >> 2, tg = lane & 3;
    #pragma unroll
    for (int mb = 0; mb < 2; mb++) {
        int r0 = rowBase + warp_m * 32 + mb * 16 + gid;
        int r1 = r0 + 8;
        #pragma unroll
        for (int nb = 0; nb < 4; nb++) {
            int col = warp_n * 32 + nb * 8 + tg * 2;
            if (r0 < NN)
                *(__half2*)&outh[(size_t)r0 * OUT_F + col] =
                    __floats2half2_rn(acc[mb][nb][0], acc[mb][nb][1]);
            if (r1 < NN)
                *(__half2*)&outh[(size_t)r1 * OUT_F + col] =
                    __floats2half2_rn(acc[mb][nb][2], acc[mb][nb][3]);
        }
    }
}

// ---------------- SpMM1 (+ ReLU + dropout + bf16 split) : warp per row ------
// gathers fp16 xw1 (16B per lane per edge), accumulates fp32.
__global__ void __launch_bounds__(256)
spmm1_kernel(const void* __restrict__ a_col,
             const float* __restrict__ a_val,
             const int* __restrict__ drop_mask) {
    int warp = (blockIdx.x * blockDim.x + threadIdx.x) >> 5;
    int lane = threadIdx.x & 31;
    if (warp >= NN) return;
    const int is64 = g_is64;
    int e0 = g_rowptr[warp];
    int e1 = g_rowptr[warp + 1];

    float acc[8];
    #pragma unroll
    for (int j = 0; j < 8; j++) acc[j] = 0.f;

    int e = e0;
    for (; e + 3 < e1; e += 4) {
        int cc[4]; float vv[4]; uint4 q[4];
        #pragma unroll
        for (int j = 0; j < 4; j++) {
            cc[j] = load_idx(a_col, e + j, is64);
            vv[j] = __ldg(&a_val[e + j]);
        }
        #pragma unroll
        for (int j = 0; j < 4; j++)
            q[j] = __ldg((const uint4*)(g_xw1h + (size_t)cc[j] * HID) + lane);
        #pragma unroll
        for (int j = 0; j < 4; j++) {
            float2 f0 = __half22float2(*reinterpret_cast<__half2*>(&q[j].x));
            float2 f1 = __half22float2(*reinterpret_cast<__half2*>(&q[j].y));
            float2 f2 = __half22float2(*reinterpret_cast<__half2*>(&q[j].z));
            float2 f3 = __half22float2(*reinterpret_cast<__half2*>(&q[j].w));
            acc[0] = fmaf(vv[j], f0.x, acc[0]); acc[1] = fmaf(vv[j], f0.y, acc[1]);
            acc[2] = fmaf(vv[j], f1.x, acc[2]); acc[3] = fmaf(vv[j], f1.y, acc[3]);
            acc[4] = fmaf(vv[j], f2.x, acc[4]); acc[5] = fmaf(vv[j], f2.y, acc[5]);
            acc[6] = fmaf(vv[j], f3.x, acc[6]); acc[7] = fmaf(vv[j], f3.y, acc[7]);
        }
    }
    for (; e < e1; e++) {
        int   col = load_idx(a_col, e, is64);
        float v   = __ldg(&a_val[e]);
        uint4 q = __ldg((const uint4*)(g_xw1h + (size_t)col * HID) + lane);
        float2 f0 = __half22float2(*reinterpret_cast<__half2*>(&q.x));
        float2 f1 = __half22float2(*reinterpret_cast<__half2*>(&q.y));
        float2 f2 = __half22float2(*reinterpret_cast<__half2*>(&q.z));
        float2 f3 = __half22float2(*reinterpret_cast<__half2*>(&q.w));
        acc[0] = fmaf(v, f0.x, acc[0]); acc[1] = fmaf(v, f0.y, acc[1]);
        acc[2] = fmaf(v, f1.x, acc[2]); acc[3] = fmaf(v, f1.y, acc[3]);
        acc[4] = fmaf(v, f2.x, acc[4]); acc[5] = fmaf(v, f2.y, acc[5]);
        acc[6] = fmaf(v, f3.x, acc[6]); acc[7] = fmaf(v, f3.y, acc[7]);
    }

    const int4* mrow = (const int4*)(drop_mask + (size_t)warp * HID) + lane * 2;
    int4 m0 = __ldg(mrow);
    int4 m1 = __ldg(mrow + 1);

    float r[8];
    r[0] = fmaxf(acc[0], 0.f) * (float)m0.x * 2.0f;
    r[1] = fmaxf(acc[1], 0.f) * (float)m0.y * 2.0f;
    r[2] = fmaxf(acc[2], 0.f) * (float)m0.z * 2.0f;
    r[3] = fmaxf(acc[3], 0.f) * (float)m0.w * 2.0f;
    r[4] = fmaxf(acc[4], 0.f) * (float)m1.x * 2.0f;
    r[5] = fmaxf(acc[5], 0.f) * (float)m1.y * 2.0f;
    r[6] = fmaxf(acc[6], 0.f) * (float)m1.z * 2.0f;
    r[7] = fmaxf(acc[7], 0.f) * (float)m1.w * 2.0f;

    uint4 hi, lo;
    float h0, h1;
    h0 = bf_round(r[0]); h1 = bf_round(r[1]);
    hi.x = bf2_pack(r[0], r[1]); lo.x = bf2_pack(r[0] - h0, r[1] - h1);
    h0 = bf_round(r[2]); h1 = bf_round(r[3]);
    hi.y = bf2_pack(r[2], r[3]); lo.y = bf2_pack(r[2] - h0, r[3] - h1);
    h0 = bf_round(r[4]); h1 = bf_round(r[5]);
    hi.z = bf2_pack(r[4], r[5]); lo.z = bf2_pack(r[4] - h0, r[5] - h1);
    h0 = bf_round(r[6]); h1 = bf_round(r[7]);
    hi.w = bf2_pack(r[6], r[7]); lo.w = bf2_pack(r[6] - h0, r[7] - h1);

    *(uint4*)(g_h_hi + (size_t)warp * HID + lane * 8) = hi;
    *(uint4*)(g_h_lo + (size_t)warp * HID + lane * 8) = lo;
}

// ---------------- SpMM2 + log_softmax : warp per row (fp16 gather) ----------
__global__ void __launch_bounds__(256)
spmm2_lsm_kernel(const void* __restrict__ a_col,
                 const float* __restrict__ a_val,
                 float* __restrict__ out) {
    int warp = (blockIdx.x * blockDim.x + threadIdx.x) >> 5;
    int lane = threadIdx.x & 31;
    if (warp >= NN) return;
    const int is64 = g_is64;
    int e0 = g_rowptr[warp];
    int e1 = g_rowptr[warp + 1];

    float a0 = 0.f, a1 = 0.f;   // cols lane*2, lane*2+1
    int e = e0;
    for (; e + 3 < e1; e += 4) {
        int cc[4]; float vv[4]; uint32_t u[4];
        #pragma unroll
        for (int j = 0; j < 4; j++) {
            cc[j] = load_idx(a_col, e + j, is64);
            vv[j] = __ldg(&a_val[e + j]);
        }
        #pragma unroll
        for (int j = 0; j < 4; j++)
            u[j] = __ldg((const uint32_t*)(g_hw2h + (size_t)cc[j] * OUT_F) + lane);
        #pragma unroll
        for (int j = 0; j < 4; j++) {
            float2 f = __half22float2(*reinterpret_cast<__half2*>(&u[j]));
            a0 = fmaf(vv[j], f.x, a0);
            a1 = fmaf(vv[j], f.y, a1);
        }
    }
    for (; e < e1; e++) {
        int   col = load_idx(a_col, e, is64);
        float v   = __ldg(&a_val[e]);
        uint32_t u = __ldg((const uint32_t*)(g_hw2h + (size_t)col * OUT_F) + lane);
        float2 f = __half22float2(*reinterpret_cast<__half2*>(&u));
        a0 = fmaf(v, f.x, a0);
        a1 = fmaf(v, f.y, a1);
    }

    float m = fmaxf(a0, a1);
    #pragma unroll
    for (int off = 16; off > 0; off >>= 1)
        m = fmaxf(m, __shfl_xor_sync(0xFFFFFFFFu, m, off));
    float s = expf(a0 - m) + expf(a1 - m);
    #pragma unroll
    for (int off = 16; off > 0; off >>= 1)
        s += __shfl_xor_sync(0xFFFFFFFFu, s, off);
    float ls = logf(s) + m;

    out[(size_t)warp * OUT_F + lane * 2]     = a0 - ls;
    out[(size_t)warp * OUT_F + lane * 2 + 1] = a1 - ls;
}

// ---------------- launch ----------------------------------------------------
extern "C" void kernel_launch(void* const* d_in, const int* in_sizes, int n_in,
                              void* d_out, int out_size) {
    const float* X     = (const float*)d_in[0];
    const float* W1    = (const float*)d_in[1];
    const float* W2    = (const float*)d_in[2];
    const void*  a_row = d_in[3];
    const void*  a_col = d_in[4];
    const float* a_val = (const float*)d_in[5];
    const int*   dmask = (const int*)d_in[6];
    float*       out   = (float*)d_out;

    const int E = in_sizes[5];

    __half *p_xw1h, *p_hw2h;
    cudaGetSymbolAddress((void**)&p_xw1h, g_xw1h);
    cudaGetSymbolAddress((void**)&p_hw2h, g_hw2h);

    static int smem_set = 0;
    if (!smem_set) {
        cudaFuncSetAttribute(gemm1_mma_kernel,
                             cudaFuncAttributeMaxDynamicSharedMemorySize, G1_TOTAL);
        cudaFuncSetAttribute(gemm2_mma_kernel,
                             cudaFuncAttributeMaxDynamicSharedMemorySize, G2SMEM_TOTAL);
        smem_set = 1;
    }

    // idx0: detect index dtype
    detect_idx_kernel<<<1, 32>>>(a_col, E);

    // idx1: merged weight preps
    prep_w_kernel<<<(IN_F * HID + HID * OUT_F + 255) / 256, 256>>>(W1, W2);

    // idx2: row pointers
    build_rowptr_kernel<<<(NN + 1 + 255) / 256, 256>>>(a_row, E);

    // idx3 (profiled slot): GEMM1 xw1 = X @ W1 -> fp16
    gemm1_mma_kernel<<<(NN + 127) / 128, 512, G1_TOTAL>>>(X, p_xw1h);

    // idx4: SpMM1 + relu + dropout -> h (bf16 hi/lo)
    spmm1_kernel<<<(NN * 32 + 255) / 256, 256>>>(a_col, a_val, dmask);

    // idx5: GEMM2 hw2 = h @ W2 -> fp16
    gemm2_mma_kernel<<<(NN + 127) / 128, 256, G2SMEM_TOTAL>>>(p_hw2h);

    // idx6: SpMM2 + log_softmax -> out
    spmm2_lsm_kernel<<<(NN * 32 + 255) / 256, 256>>>(a_col, a_val, out);
}

// round 9
// speedup vs baseline: 2.2061x; 1.0916x over previous
#include <cuda_runtime.h>
#include <cuda_bf16.h>
#include <cuda_fp16.h>
#include <math.h>
#include <stdint.h>

// Problem constants
#define NN    50000
#define EE    800000
#define IN_F  512
#define HID   256
#define OUT_F 64

// ---------------- scratch (static device globals; no allocs) ----------------
__device__ __half g_xw1h[(size_t)NN * HID];   // X @ W1 (fp16 gather table)
__device__ __half g_hw2h[(size_t)NN * OUT_F]; // h @ W2 (fp16 gather table)
__device__ int   g_rowptr[NN + 1];
__device__ int   g_is64;
__device__ __nv_bfloat16 g_w1t_hi[(size_t)HID * IN_F]; // W1^T bf16 hi [256,512]
__device__ __nv_bfloat16 g_w1t_lo[(size_t)HID * IN_F]; // W1^T bf16 lo
__device__ __nv_bfloat16 g_h_hi[(size_t)NN * HID];     // h split hi [50000,256]
__device__ __nv_bfloat16 g_h_lo[(size_t)NN * HID];     // h split lo
__device__ __nv_bfloat16 g_w2t_hi[(size_t)OUT_F * HID]; // W2^T bf16 hi [64,256]
__device__ __nv_bfloat16 g_w2t_lo[(size_t)OUT_F * HID]; // W2^T bf16 lo

// ======================= PTX helpers ========================================
__device__ __forceinline__ uint32_t smem_u32(const void* p) {
    uint32_t a;
    asm("{ .reg .u64 t; cvta.to.shared.u64 t, %1; cvt.u32.u64 %0, t; }"
        : "=r"(a) : "l"(p));
    return a;
}
__device__ __forceinline__ void cpa16(uint32_t dst, const void* src) {
    asm volatile("cp.async.cg.shared.global [%0], [%1], 16;"
                 :: "r"(dst), "l"(src) : "memory");
}
#define CP_COMMIT()  asm volatile("cp.async.commit_group;" ::: "memory")
#define CP_WAIT_1()  asm volatile("cp.async.wait_group 1;" ::: "memory")
#define CP_WAIT_0()  asm volatile("cp.async.wait_group 0;" ::: "memory")

__device__ __forceinline__ void ldsm_x4(uint32_t& r0, uint32_t& r1,
                                        uint32_t& r2, uint32_t& r3, uint32_t addr) {
    asm volatile("ldmatrix.sync.aligned.m8n8.x4.shared.b16 {%0,%1,%2,%3}, [%4];"
                 : "=r"(r0), "=r"(r1), "=r"(r2), "=r"(r3) : "r"(addr));
}
__device__ __forceinline__ void mma_bf16_2(float* c, const uint32_t* a,
                                           uint32_t b0, uint32_t b1) {
    asm volatile(
        "mma.sync.aligned.m16n8k16.row.col.f32.bf16.bf16.f32 "
        "{%0,%1,%2,%3}, {%4,%5,%6,%7}, {%8,%9}, {%0,%1,%2,%3};"
        : "+f"(c[0]), "+f"(c[1]), "+f"(c[2]), "+f"(c[3])
        : "r"(a[0]), "r"(a[1]), "r"(a[2]), "r"(a[3]), "r"(b0), "r"(b1));
}
__device__ __forceinline__ uint32_t bf2_pack(float a, float b) {
    __nv_bfloat162 t = __floats2bfloat162_rn(a, b);
    return *reinterpret_cast<uint32_t*>(&t);
}
__device__ __forceinline__ float bf_round(float x) {
    return __bfloat162float(__float2bfloat16_rn(x));
}
__device__ __forceinline__ uint32_t h2_pack(float a, float b) {
    __half2 t = __floats2half2_rn(a, b);
    return *reinterpret_cast<uint32_t*>(&t);
}

// ---------------- index dtype detection (int64 vs int32) --------------------
__global__ void detect_idx_kernel(const void* __restrict__ a_col_raw, int E) {
    if (threadIdx.x != 0 || blockIdx.x != 0) return;
    const long long* p = (const long long*)a_col_raw;
    int ok = 1;
    for (int i = 0; i < 16; i++) {
        long long v = p[i];
        if (v < 0 || v >= NN) { ok = 0; break; }
    }
    if (ok) {
        for (int i = 0; i < 16; i++) {
            long long v = p[E / 2 + i];
            if (v < 0 || v >= NN) { ok = 0; break; }
        }
    }
    g_is64 = ok;
}
__device__ __forceinline__ int load_idx(const void* p, int i, int is64) {
    if (is64) return (int)((const long long*)p)[i];
    return ((const int*)p)[i];
}

// ---------------- merged weight prep (bf16 hi/lo) ----------------------------
__global__ void prep_w_kernel(const float* __restrict__ W1,
                              const float* __restrict__ W2) {
    int idx = blockIdx.x * blockDim.x + threadIdx.x;
    if (idx < IN_F * HID) {
        int n = idx >> 9, k = idx & 511;
        float v = W1[(size_t)k * HID + n];
        __nv_bfloat16 h = __float2bfloat16_rn(v);
        g_w1t_hi[idx] = h;
        g_w1t_lo[idx] = __float2bfloat16_rn(v - __bfloat162float(h));
    } else {
        int j = idx - IN_F * HID;
        if (j < HID * OUT_F) {
            int n = j >> 8, k = j & 255;
            float v = W2[(size_t)k * OUT_F + n];
            __nv_bfloat16 h = __float2bfloat16_rn(v);
            g_w2t_hi[j] = h;
            g_w2t_lo[j] = __float2bfloat16_rn(v - __bfloat162float(h));
        }
    }
}

// ---------------- rowptr ----------------------------------------------------
__global__ void build_rowptr_kernel(const void* __restrict__ a_row, int E) {
    int r = blockIdx.x * blockDim.x + threadIdx.x;
    if (r > NN) return;
    if (r == NN) { g_rowptr[NN] = E; return; }
    const int is64 = g_is64;
    int lo = 0, hi = E;
    while (lo < hi) {
        int mid = (lo + hi) >> 1;
        if (load_idx(a_row, mid, is64) < r) lo = mid + 1; else hi = mid;
    }
    g_rowptr[r] = lo;
}

// ---------------- GEMM1: X@W1 CTA 128x128, bf16 3-term, reg-staged X --------
// 256 threads, 8 warps: warp_m = wid&3 (32 rows), warp_n = wid>>2 (64 cols).
// smem 80KB -> 2 CTAs/SM. X fp32 -> regs (prefetch) -> bf16 hi/lo smem.
#define ROWB   80
#define G1_AHI 0          // 2 x 10240
#define G1_ALO 20480
#define G1_BHI 40960
#define G1_BLO 61440
#define G1_TOTAL 81920

__global__ void __launch_bounds__(256, 2)
gemm1_mma_kernel(const float* __restrict__ X, __half* __restrict__ outh) {
    extern __shared__ char smem[];
    const uint32_t sm0 = smem_u32(smem);
    const int tid = threadIdx.x;
    const int wid = tid >> 5, lane = tid & 31;
    const int warp_m = wid & 3, warp_n = wid >> 2;
    const int colBase = blockIdx.x * 128;   // 0 or 128 (HID)
    const int rowBase = blockIdx.y * 128;

    float acc[2][8][4];
    #pragma unroll
    for (int i = 0; i < 2; i++)
        #pragma unroll
        for (int j = 0; j < 8; j++)
            #pragma unroll
            for (int t = 0; t < 4; t++) acc[i][j][t] = 0.f;

    const int xrow = tid >> 3;   // 0..31 (+32i)
    const int xq   = tid & 7;    // 16B chunk in 128B row
    float4 xr[4];

    auto ldg_x = [&](int kc) {
        int k0 = kc * 32;
        #pragma unroll
        for (int i = 0; i < 4; i++) {
            int rg = rowBase + xrow + 32 * i;
            if (rg >= NN) rg = NN - 1;
            xr[i] = __ldg((const float4*)(X + (size_t)rg * IN_F + k0 + xq * 4));
        }
    };
    auto convert_x = [&](int s) {
        char* ah = smem + G1_AHI + s * 10240;
        char* al = smem + G1_ALO + s * 10240;
        #pragma unroll
        for (int i = 0; i < 4; i++) {
            int row = xrow + 32 * i;
            float4 v = xr[i];
            float h0 = bf_round(v.x), h1 = bf_round(v.y);
            float h2 = bf_round(v.z), h3 = bf_round(v.w);
            uint2 hi = make_uint2(bf2_pack(v.x, v.y), bf2_pack(v.z, v.w));
            uint2 lo = make_uint2(bf2_pack(v.x - h0, v.y - h1),
                                  bf2_pack(v.z - h2, v.w - h3));
            *(uint2*)(ah + row * ROWB + xq * 8) = hi;
            *(uint2*)(al + row * ROWB + xq * 8) = lo;
        }
    };
    auto load_b = [&](int s, int kc) {
        int k0 = kc * 32;
        uint32_t bh = sm0 + G1_BHI + s * 10240;
        uint32_t bl = sm0 + G1_BLO + s * 10240;
        #pragma unroll
        for (int i = 0; i < 2; i++) {
            int c = tid + 256 * i;          // 0..511 : 128 B-rows x 4 chunks
            int row = c >> 2, q = c & 3;
            uint32_t o = row * ROWB + q * 16;
            cpa16(bh + o, g_w1t_hi + (size_t)(colBase + row) * IN_F + k0 + q * 8);
            cpa16(bl + o, g_w1t_lo + (size_t)(colBase + row) * IN_F + k0 + q * 8);
        }
    };

    const int lq = lane >> 3, lr = lane & 7;

    auto compute_stage = [&](int s) {
        uint32_t ah = sm0 + G1_AHI + s * 10240;
        uint32_t al = sm0 + G1_ALO + s * 10240;
        uint32_t bhb = sm0 + G1_BHI + s * 10240;
        uint32_t blb = sm0 + G1_BLO + s * 10240;
        #pragma unroll
        for (int ks = 0; ks < 2; ks++) {
            uint32_t ahi[2][4], alo[2][4];
            #pragma unroll
            for (int mb = 0; mb < 2; mb++) {
                int row = warp_m * 32 + mb * 16 + (lq & 1) * 8 + lr;
                int kb  = ks * 32 + (lq >> 1) * 16;
                ldsm_x4(ahi[mb][0], ahi[mb][1], ahi[mb][2], ahi[mb][3],
                        ah + row * ROWB + kb);
                ldsm_x4(alo[mb][0], alo[mb][1], alo[mb][2], alo[mb][3],
                        al + row * ROWB + kb);
            }
            #pragma unroll
            for (int g = 0; g < 4; g++) {
                int row = warp_n * 64 + g * 16 + (lq >> 1) * 8 + lr;
                int kb  = ks * 32 + (lq & 1) * 16;
                uint32_t o = row * ROWB + kb;
                uint32_t bh0, bh1, bh2, bh3, bl0, bl1, bl2, bl3;
                ldsm_x4(bh0, bh1, bh2, bh3, bhb + o);
                ldsm_x4(bl0, bl1, bl2, bl3, blb + o);
                #pragma unroll
                for (int mb = 0; mb < 2; mb++) {
                    mma_bf16_2(acc[mb][2*g],   ahi[mb], bh0, bh1);
                    mma_bf16_2(acc[mb][2*g],   ahi[mb], bl0, bl1);
                    mma_bf16_2(acc[mb][2*g],   alo[mb], bh0, bh1);
                    mma_bf16_2(acc[mb][2*g+1], ahi[mb], bh2, bh3);
                    mma_bf16_2(acc[mb][2*g+1], ahi[mb], bl2, bl3);
                    mma_bf16_2(acc[mb][2*g+1], alo[mb], bh2, bh3);
                }
            }
        }
    };

    load_b(0, 0); CP_COMMIT();
    ldg_x(0);
    for (int kc = 0; kc < 16; kc++) {
        if (kc < 15) { load_b((kc + 1) & 1, kc + 1); CP_COMMIT(); }
        convert_x(kc & 1);              // own regs -> smem (self-consistent)
        if (kc < 15) ldg_x(kc + 1);     // prefetch next X chunk into regs
        if (kc < 15) CP_WAIT_1(); else CP_WAIT_0();
        __syncthreads();                // publish A converts + B(kc)
        compute_stage(kc & 1);
        __syncthreads();                // protect B/A buffers from next writes
    }

    const int gid = lane >> 2, tg = lane & 3;
    #pragma unroll
    for (int mb = 0; mb < 2; mb++) {
        int r0 = rowBase + warp_m * 32 + mb * 16 + gid;
        int r1 = r0 + 8;
        #pragma unroll
        for (int nb = 0; nb < 8; nb++) {
            int col = colBase + warp_n * 64 + nb * 8 + tg * 2;
            if (r0 < NN)
                *(__half2*)&outh[(size_t)r0 * HID + col] =
                    __floats2half2_rn(acc[mb][nb][0], acc[mb][nb][1]);
            if (r1 < NN)
                *(__half2*)&outh[(size_t)r1 * HID + col] =
                    __floats2half2_rn(acc[mb][nb][2], acc[mb][nb][3]);
        }
    }
}

// ---------------- GEMM2 via mma.sync bf16 (3-term split) --------------------
#define S2_A_HI 0
#define S2_A_LO 10240
#define S2_B_HI 20480
#define S2_B_LO 25600
#define STG2    30720
#define G2_TOTAL (2 * STG2)   // 61440

__global__ void __launch_bounds__(256)
gemm2_mma_kernel(__half* __restrict__ outh) {
    extern __shared__ char smem[];
    const uint32_t sm0 = smem_u32(smem);
    const int tid = threadIdx.x;
    const int wid = tid >> 5, lane = tid & 31;
    const int warp_m = wid & 3, warp_n = wid >> 2;
    const int rowBase = blockIdx.x * 128;

    float acc[2][4][4];
    #pragma unroll
    for (int i = 0; i < 2; i++)
        #pragma unroll
        for (int j = 0; j < 4; j++)
            #pragma unroll
            for (int t = 0; t < 4; t++) acc[i][j][t] = 0.f;

    auto load_stage = [&](int s, int kc) {
        int k0 = kc * 32;
        uint32_t sb = sm0 + s * STG2;
        #pragma unroll
        for (int i = 0; i < 2; i++) {
            int c = tid + 256 * i;
            int row = c >> 2, q = c & 3;
            int rg = rowBase + row; if (rg >= NN) rg = NN - 1;
            uint32_t o = row * ROWB + q * 16;
            cpa16(sb + S2_A_HI + o, g_h_hi + (size_t)rg * HID + k0 + q * 8);
            cpa16(sb + S2_A_LO + o, g_h_lo + (size_t)rg * HID + k0 + q * 8);
        }
        {
            int row = tid >> 2, q = tid & 3;
            uint32_t o = row * ROWB + q * 16;
            cpa16(sb + S2_B_HI + o, g_w2t_hi + (size_t)row * HID + k0 + q * 8);
            cpa16(sb + S2_B_LO + o, g_w2t_lo + (size_t)row * HID + k0 + q * 8);
        }
    };

    const int lq = lane >> 3, lr = lane & 7;

    auto compute_stage = [&](int s) {
        uint32_t sb = sm0 + s * STG2;
        #pragma unroll
        for (int ks = 0; ks < 2; ks++) {
            uint32_t ahi[2][4], alo[2][4];
            #pragma unroll
            for (int mb = 0; mb < 2; mb++) {
                int row = warp_m * 32 + mb * 16 + (lq & 1) * 8 + lr;
                int kb  = ks * 32 + (lq >> 1) * 16;
                uint32_t o = row * ROWB + kb;
                ldsm_x4(ahi[mb][0], ahi[mb][1], ahi[mb][2], ahi[mb][3], sb + S2_A_HI + o);
                ldsm_x4(alo[mb][0], alo[mb][1], alo[mb][2], alo[mb][3], sb + S2_A_LO + o);
            }
            #pragma unroll
            for (int g = 0; g < 2; g++) {
                int row = warp_n * 32 + g * 16 + (lq >> 1) * 8 + lr;
                int kb  = ks * 32 + (lq & 1) * 16;
                uint32_t o = row * ROWB + kb;
                uint32_t bh0, bh1, bh2, bh3, bl0, bl1, bl2, bl3;
                ldsm_x4(bh0, bh1, bh2, bh3, sb + S2_B_HI + o);
                ldsm_x4(bl0, bl1, bl2, bl3, sb + S2_B_LO + o);
                #pragma unroll
                for (int mb = 0; mb < 2; mb++) {
                    mma_bf16_2(acc[mb][2*g],   ahi[mb], bh0, bh1);
                    mma_bf16_2(acc[mb][2*g],   ahi[mb], bl0, bl1);
                    mma_bf16_2(acc[mb][2*g],   alo[mb], bh0, bh1);
                    mma_bf16_2(acc[mb][2*g+1], ahi[mb], bh2, bh3);
                    mma_bf16_2(acc[mb][2*g+1], ahi[mb], bl2, bl3);
                    mma_bf16_2(acc[mb][2*g+1], alo[mb], bh2, bh3);
                }
            }
        }
    };

    load_stage(0, 0);
    CP_COMMIT();
    for (int kc = 0; kc < 8; kc++) {
        if (kc < 7) {
            load_stage((kc + 1) & 1, kc + 1);
            CP_COMMIT();
            CP_WAIT_1();
        } else {
            CP_WAIT_0();
        }
        __syncthreads();
        compute_stage(kc & 1);
        __syncthreads();
    }

    const int gid = lane >> 2, tg = lane & 3;
    #pragma unroll
    for (int mb = 0; mb < 2; mb++) {
        int r0 = rowBase + warp_m * 32 + mb * 16 + gid;
        int r1 = r0 + 8;
        #pragma unroll
        for (int nb = 0; nb < 4; nb++) {
            int col = warp_n * 32 + nb * 8 + tg * 2;
            if (r0 < NN)
                *(__half2*)&outh[(size_t)r0 * OUT_F + col] =
                    __floats2half2_rn(acc[mb][nb][0], acc[mb][nb][1]);
            if (r1 < NN)
                *(__half2*)&outh[(size_t)r1 * OUT_F + col] =
                    __floats2half2_rn(acc[mb][nb][2], acc[mb][nb][3]);
        }
    }
}

// ---------------- SpMM1 (+ ReLU + dropout + bf16 split) : warp per row ------
__global__ void __launch_bounds__(256)
spmm1_kernel(const void* __restrict__ a_col,
             const float* __restrict__ a_val,
             const int* __restrict__ drop_mask) {
    int warp = (blockIdx.x * blockDim.x + threadIdx.x) >> 5;
    int lane = threadIdx.x & 31;
    if (warp >= NN) return;
    const int is64 = g_is64;
    int e0 = g_rowptr[warp];
    int e1 = g_rowptr[warp + 1];

    float acc[8];
    #pragma unroll
    for (int j = 0; j < 8; j++) acc[j] = 0.f;

    int e = e0;
    for (; e + 3 < e1; e += 4) {
        int cc[4]; float vv[4]; uint4 q[4];
        #pragma unroll
        for (int j = 0; j < 4; j++) {
            cc[j] = load_idx(a_col, e + j, is64);
            vv[j] = __ldg(&a_val[e + j]);
        }
        #pragma unroll
        for (int j = 0; j < 4; j++)
            q[j] = __ldg((const uint4*)(g_xw1h + (size_t)cc[j] * HID) + lane);
        #pragma unroll
        for (int j = 0; j < 4; j++) {
            float2 f0 = __half22float2(*reinterpret_cast<__half2*>(&q[j].x));
            float2 f1 = __half22float2(*reinterpret_cast<__half2*>(&q[j].y));
            float2 f2 = __half22float2(*reinterpret_cast<__half2*>(&q[j].z));
            float2 f3 = __half22float2(*reinterpret_cast<__half2*>(&q[j].w));
            acc[0] = fmaf(vv[j], f0.x, acc[0]); acc[1] = fmaf(vv[j], f0.y, acc[1]);
            acc[2] = fmaf(vv[j], f1.x, acc[2]); acc[3] = fmaf(vv[j], f1.y, acc[3]);
            acc[4] = fmaf(vv[j], f2.x, acc[4]); acc[5] = fmaf(vv[j], f2.y, acc[5]);
            acc[6] = fmaf(vv[j], f3.x, acc[6]); acc[7] = fmaf(vv[j], f3.y, acc[7]);
        }
    }
    for (; e < e1; e++) {
        int   col = load_idx(a_col, e, is64);
        float v   = __ldg(&a_val[e]);
        uint4 q = __ldg((const uint4*)(g_xw1h + (size_t)col * HID) + lane);
        float2 f0 = __half22float2(*reinterpret_cast<__half2*>(&q.x));
        float2 f1 = __half22float2(*reinterpret_cast<__half2*>(&q.y));
        float2 f2 = __half22float2(*reinterpret_cast<__half2*>(&q.z));
        float2 f3 = __half22float2(*reinterpret_cast<__half2*>(&q.w));
        acc[0] = fmaf(v, f0.x, acc[0]); acc[1] = fmaf(v, f0.y, acc[1]);
        acc[2] = fmaf(v, f1.x, acc[2]); acc[3] = fmaf(v, f1.y, acc[3]);
        acc[4] = fmaf(v, f2.x, acc[4]); acc[5] = fmaf(v, f2.y, acc[5]);
        acc[6] = fmaf(v, f3.x, acc[6]); acc[7] = fmaf(v, f3.y, acc[7]);
    }

    const int4* mrow = (const int4*)(drop_mask + (size_t)warp * HID) + lane * 2;
    int4 m0 = __ldg(mrow);
    int4 m1 = __ldg(mrow + 1);

    float r[8];
    r[0] = fmaxf(acc[0], 0.f) * (float)m0.x * 2.0f;
    r[1] = fmaxf(acc[1], 0.f) * (float)m0.y * 2.0f;
    r[2] = fmaxf(acc[2], 0.f) * (float)m0.z * 2.0f;
    r[3] = fmaxf(acc[3], 0.f) * (float)m0.w * 2.0f;
    r[4] = fmaxf(acc[4], 0.f) * (float)m1.x * 2.0f;
    r[5] = fmaxf(acc[5], 0.f) * (float)m1.y * 2.0f;
    r[6] = fmaxf(acc[6], 0.f) * (float)m1.z * 2.0f;
    r[7] = fmaxf(acc[7], 0.f) * (float)m1.w * 2.0f;

    uint4 hi, lo;
    float h0, h1;
    h0 = bf_round(r[0]); h1 = bf_round(r[1]);
    hi.x = bf2_pack(r[0], r[1]); lo.x = bf2_pack(r[0] - h0, r[1] - h1);
    h0 = bf_round(r[2]); h1 = bf_round(r[3]);
    hi.y = bf2_pack(r[2], r[3]); lo.y = bf2_pack(r[2] - h0, r[3] - h1);
    h0 = bf_round(r[4]); h1 = bf_round(r[5]);
    hi.z = bf2_pack(r[4], r[5]); lo.z = bf2_pack(r[4] - h0, r[5] - h1);
    h0 = bf_round(r[6]); h1 = bf_round(r[7]);
    hi.w = bf2_pack(r[6], r[7]); lo.w = bf2_pack(r[6] - h0, r[7] - h1);

    *(uint4*)(g_h_hi + (size_t)warp * HID + lane * 8) = hi;
    *(uint4*)(g_h_lo + (size_t)warp * HID + lane * 8) = lo;
}

// ---------------- SpMM2 + log_softmax : warp per row (fp16 gather) ----------
__global__ void __launch_bounds__(256)
spmm2_lsm_kernel(const void* __restrict__ a_col,
                 const float* __restrict__ a_val,
                 float* __restrict__ out) {
    int warp = (blockIdx.x * blockDim.x + threadIdx.x) >> 5;
    int lane = threadIdx.x & 31;
    if (warp >= NN) return;
    const int is64 = g_is64;
    int e0 = g_rowptr[warp];
    int e1 = g_rowptr[warp + 1];

    float a0 = 0.f, a1 = 0.f;
    int e = e0;
    for (; e + 3 < e1; e += 4) {
        int cc[4]; float vv[4]; uint32_t u[4];
        #pragma unroll
        for (int j = 0; j < 4; j++) {
            cc[j] = load_idx(a_col, e + j, is64);
            vv[j] = __ldg(&a_val[e + j]);
        }
        #pragma unroll
        for (int j = 0; j < 4; j++)
            u[j] = __ldg((const uint32_t*)(g_hw2h + (size_t)cc[j] * OUT_F) + lane);
        #pragma unroll
        for (int j = 0; j < 4; j++) {
            float2 f = __half22float2(*reinterpret_cast<__half2*>(&u[j]));
            a0 = fmaf(vv[j], f.x, a0);
            a1 = fmaf(vv[j], f.y, a1);
        }
    }
    for (; e < e1; e++) {
        int   col = load_idx(a_col, e, is64);
        float v   = __ldg(&a_val[e]);
        uint32_t u = __ldg((const uint32_t*)(g_hw2h + (size_t)col * OUT_F) + lane);
        float2 f = __half22float2(*reinterpret_cast<__half2*>(&u));
        a0 = fmaf(v, f.x, a0);
        a1 = fmaf(v, f.y, a1);
    }

    float m = fmaxf(a0, a1);
    #pragma unroll
    for (int off = 16; off > 0; off >>= 1)
        m = fmaxf(m, __shfl_xor_sync(0xFFFFFFFFu, m, off));
    float s = expf(a0 - m) + expf(a1 - m);
    #pragma unroll
    for (int off = 16; off > 0; off >>= 1)
        s += __shfl_xor_sync(0xFFFFFFFFu, s, off);
    float ls = logf(s) + m;

    out[(size_t)warp * OUT_F + lane * 2]     = a0 - ls;
    out[(size_t)warp * OUT_F + lane * 2 + 1] = a1 - ls;
}

// ---------------- launch ----------------------------------------------------
extern "C" void kernel_launch(void* const* d_in, const int* in_sizes, int n_in,
                              void* d_out, int out_size) {
    const float* X     = (const float*)d_in[0];
    const float* W1    = (const float*)d_in[1];
    const float* W2    = (const float*)d_in[2];
    const void*  a_row = d_in[3];
    const void*  a_col = d_in[4];
    const float* a_val = (const float*)d_in[5];
    const int*   dmask = (const int*)d_in[6];
    float*       out   = (float*)d_out;

    const int E = in_sizes[5];

    __half *p_xw1h, *p_hw2h;
    cudaGetSymbolAddress((void**)&p_xw1h, g_xw1h);
    cudaGetSymbolAddress((void**)&p_hw2h, g_hw2h);

    static int smem_set = 0;
    if (!smem_set) {
        cudaFuncSetAttribute(gemm1_mma_kernel,
                             cudaFuncAttributeMaxDynamicSharedMemorySize, G1_TOTAL);
        cudaFuncSetAttribute(gemm2_mma_kernel,
                             cudaFuncAttributeMaxDynamicSharedMemorySize, G2_TOTAL);
        smem_set = 1;
    }

    // idx0: detect index dtype
    detect_idx_kernel<<<1, 32>>>(a_col, E);

    // idx1: merged weight preps
    prep_w_kernel<<<(IN_F * HID + HID * OUT_F + 255) / 256, 256>>>(W1, W2);

    // idx2: row pointers
    build_rowptr_kernel<<<(NN + 1 + 255) / 256, 256>>>(a_row, E);

    // idx3 (profiled slot): GEMM1 xw1 = X @ W1 -> fp16
    {
        dim3 grid(HID / 128, (NN + 127) / 128);   // x-major: N-pair shares X via L2
        gemm1_mma_kernel<<<grid, 256, G1_TOTAL>>>(X, p_xw1h);
    }

    // idx4: SpMM1 + relu + dropout -> h (bf16 hi/lo)
    spmm1_kernel<<<(NN * 32 + 255) / 256, 256>>>(a_col, a_val, dmask);

    // idx5: GEMM2 hw2 = h @ W2 -> fp16
    gemm2_mma_kernel<<<(NN + 127) / 128, 256, G2_TOTAL>>>(p_hw2h);

    // idx6: SpMM2 + log_softmax -> out
    spmm2_lsm_kernel<<<(NN * 32 + 255) / 256, 256>>>(a_col, a_val, out);
}